// round 3
// baseline (speedup 1.0000x reference)
#include <cuda_runtime.h>
#include <cuda_bf16.h>

// ---------------------------------------------------------------------------
// DifferentialAttention  (B=1, S=2048, D=2048, H=16, DH=64)
// fp32 baseline: tiled SGEMMs + batched QK/PV + fused softmax-combine + GN.
// All scratch is __device__ global (no allocations, graph-capturable).
// ---------------------------------------------------------------------------

#define SEQ     2048
#define DMODEL  2048
#define NHEAD   16
#define DHEAD   64
#define LAMBDA_INIT 0.8f

static const long long SMAT = (long long)SEQ * SEQ;   // one score matrix (4M elems)

__device__ float g_Q[SEQ * DMODEL];
__device__ float g_K[SEQ * DMODEL];
__device__ float g_V[SEQ * DMODEL];
__device__ float g_S[32ll * SEQ * SEQ];               // [head*2+variant][s][t], 512 MB
__device__ float g_AO[SEQ * DMODEL];                  // attn out [s][h*128+d]
__device__ float g_lambda;

// ---------------------------------------------------------------------------
// Generic 128x128 tile SGEMM, C = A * B (both row-major), TK = 8.
// Per-z batch offsets allow reuse for the head-batched PV GEMM.
// ---------------------------------------------------------------------------
__global__ __launch_bounds__(256, 2)
void gemm_tile128(const float* __restrict__ A, int lda, long long aBatch,
                  const float* __restrict__ B, int ldb, long long bBatch,
                  float* __restrict__ C, int ldc, long long cBatch,
                  int K)
{
    A += (long long)blockIdx.z * aBatch;
    B += (long long)blockIdx.z * bBatch;
    C += (long long)blockIdx.z * cBatch;

    __shared__ float As[8][128];
    __shared__ float Bs[8][128];

    const int tid = threadIdx.x;
    const int tx  = tid & 15;
    const int ty  = tid >> 4;
    const int row0 = blockIdx.y * 128;
    const int col0 = blockIdx.x * 128;

    // A-tile loader: 128 rows x 8 cols, one float4 per thread
    const int arow = tid >> 1;
    const int acol = (tid & 1) * 4;
    // B-tile loader: 8 rows x 128 cols, one float4 per thread
    const int brow = tid >> 5;
    const int bcol = (tid & 31) * 4;

    const float* Ap = A + (long long)(row0 + arow) * lda + acol;
    const float* Bp = B + (long long)brow * ldb + col0 + bcol;

    float acc[8][8];
#pragma unroll
    for (int i = 0; i < 8; i++)
#pragma unroll
        for (int j = 0; j < 8; j++) acc[i][j] = 0.0f;

    for (int k0 = 0; k0 < K; k0 += 8) {
        float4 av = *(const float4*)(Ap + k0);
        float4 bv = *(const float4*)(Bp + (long long)k0 * ldb);
        As[acol + 0][arow] = av.x;
        As[acol + 1][arow] = av.y;
        As[acol + 2][arow] = av.z;
        As[acol + 3][arow] = av.w;
        *(float4*)&Bs[brow][bcol] = bv;
        __syncthreads();

#pragma unroll
        for (int kk = 0; kk < 8; kk++) {
            float a[8], b[8];
            *(float4*)&a[0] = *(const float4*)&As[kk][ty * 8];
            *(float4*)&a[4] = *(const float4*)&As[kk][ty * 8 + 4];
            *(float4*)&b[0] = *(const float4*)&Bs[kk][tx * 8];
            *(float4*)&b[4] = *(const float4*)&Bs[kk][tx * 8 + 4];
#pragma unroll
            for (int i = 0; i < 8; i++)
#pragma unroll
                for (int j = 0; j < 8; j++)
                    acc[i][j] = fmaf(a[i], b[j], acc[i][j]);
        }
        __syncthreads();
    }

#pragma unroll
    for (int i = 0; i < 8; i++) {
        float* cp = C + (long long)(row0 + ty * 8 + i) * ldc + col0 + tx * 8;
        *(float4*)cp       = make_float4(acc[i][0], acc[i][1], acc[i][2], acc[i][3]);
        *(float4*)(cp + 4) = make_float4(acc[i][4], acc[i][5], acc[i][6], acc[i][7]);
    }
}

// ---------------------------------------------------------------------------
// Batched QK^T: z = head*2 + variant.  S[z][s][t] = scale * dot(Q_z[s,:], K_z[t,:])
// K-dim = 64, processed in two 32-wide chunks resident in smem.
// ---------------------------------------------------------------------------
__global__ __launch_bounds__(256, 2)
void qk_kernel()
{
    const int z = blockIdx.z;
    const int coloff = (z >> 1) * 128 + (z & 1) * 64;
    float* __restrict__ Cout = g_S + (long long)z * SMAT;
    const int t0 = blockIdx.x * 128;
    const int s0 = blockIdx.y * 128;

    __shared__ float Qs[32][128];   // [k][s]
    __shared__ float Ks[32][128];   // [k][t]

    const int tid = threadIdx.x;
    const int tx  = tid & 15;
    const int ty  = tid >> 4;

    float acc[8][8];
#pragma unroll
    for (int i = 0; i < 8; i++)
#pragma unroll
        for (int j = 0; j < 8; j++) acc[i][j] = 0.0f;

    for (int k0 = 0; k0 < 64; k0 += 32) {
#pragma unroll
        for (int l = 0; l < 4; l++) {
            int f = tid + l * 256;
            int r = f >> 3;           // 0..127
            int c = (f & 7) * 4;      // 0..28
            float4 q  = *(const float4*)(g_Q + (long long)(s0 + r) * DMODEL + coloff + k0 + c);
            float4 kv = *(const float4*)(g_K + (long long)(t0 + r) * DMODEL + coloff + k0 + c);
            Qs[c + 0][r] = q.x;  Qs[c + 1][r] = q.y;
            Qs[c + 2][r] = q.z;  Qs[c + 3][r] = q.w;
            Ks[c + 0][r] = kv.x; Ks[c + 1][r] = kv.y;
            Ks[c + 2][r] = kv.z; Ks[c + 3][r] = kv.w;
        }
        __syncthreads();

#pragma unroll 8
        for (int kk = 0; kk < 32; kk++) {
            float a[8], b[8];
            *(float4*)&a[0] = *(const float4*)&Qs[kk][ty * 8];
            *(float4*)&a[4] = *(const float4*)&Qs[kk][ty * 8 + 4];
            *(float4*)&b[0] = *(const float4*)&Ks[kk][tx * 8];
            *(float4*)&b[4] = *(const float4*)&Ks[kk][tx * 8 + 4];
#pragma unroll
            for (int i = 0; i < 8; i++)
#pragma unroll
                for (int j = 0; j < 8; j++)
                    acc[i][j] = fmaf(a[i], b[j], acc[i][j]);
        }
        __syncthreads();
    }

    const float scale = 0.125f;  // 1/sqrt(64)
#pragma unroll
    for (int i = 0; i < 8; i++) {
        float* cp = Cout + (long long)(s0 + ty * 8 + i) * SEQ + t0 + tx * 8;
        *(float4*)cp       = make_float4(acc[i][0] * scale, acc[i][1] * scale,
                                         acc[i][2] * scale, acc[i][3] * scale);
        *(float4*)(cp + 4) = make_float4(acc[i][4] * scale, acc[i][5] * scale,
                                         acc[i][6] * scale, acc[i][7] * scale);
    }
}

// ---------------------------------------------------------------------------
// lambda = exp(sum(lq1*lk1)) - exp(sum(lq2*lk2)) + 0.8
// ---------------------------------------------------------------------------
__global__ void lambda_kernel(const float* __restrict__ lq1, const float* __restrict__ lk1,
                              const float* __restrict__ lq2, const float* __restrict__ lk2)
{
    if (threadIdx.x == 0) {
        float s1 = 0.0f, s2 = 0.0f;
        for (int i = 0; i < DHEAD; i++) {
            s1 += lq1[i] * lk1[i];
            s2 += lq2[i] * lk2[i];
        }
        g_lambda = expf(s1) - expf(s2) + LAMBDA_INIT;
    }
}

// ---------------------------------------------------------------------------
// Per-row softmax of both score variants + combine: P = p1 - lam*p2.
// Row (2048 floats x 2) lives entirely in registers (8 per thread per row).
// Writes P in-place into the variant-0 slot of g_S.
// ---------------------------------------------------------------------------
__device__ __forceinline__ float block_reduce(float v, float* red, bool ismax)
{
#pragma unroll
    for (int o = 16; o; o >>= 1) {
        float ov = __shfl_xor_sync(0xffffffffu, v, o);
        v = ismax ? fmaxf(v, ov) : (v + ov);
    }
    __syncthreads();
    if ((threadIdx.x & 31) == 0) red[threadIdx.x >> 5] = v;
    __syncthreads();
    float r = red[0];
#pragma unroll
    for (int i = 1; i < 8; i++) r = ismax ? fmaxf(r, red[i]) : (r + red[i]);
    return r;
}

__global__ __launch_bounds__(256)
void softmax_combine_kernel()
{
    const int s = blockIdx.x;
    const int h = blockIdx.y;
    const int tid = threadIdx.x;

    float* __restrict__ r1 = g_S + (long long)(2 * h) * SMAT + (long long)s * SEQ;
    float* __restrict__ r2 = r1 + SMAT;

    __shared__ float red[8];

    float4 a0 = ((const float4*)r1)[2 * tid];
    float4 a1 = ((const float4*)r1)[2 * tid + 1];
    float4 b0 = ((const float4*)r2)[2 * tid];
    float4 b1 = ((const float4*)r2)[2 * tid + 1];
    float v1[8] = {a0.x, a0.y, a0.z, a0.w, a1.x, a1.y, a1.z, a1.w};
    float v2[8] = {b0.x, b0.y, b0.z, b0.w, b1.x, b1.y, b1.z, b1.w};

    float m1 = -1e30f, m2 = -1e30f;
#pragma unroll
    for (int i = 0; i < 8; i++) { m1 = fmaxf(m1, v1[i]); m2 = fmaxf(m2, v2[i]); }
    m1 = block_reduce(m1, red, true);
    __syncthreads();
    m2 = block_reduce(m2, red, true);
    __syncthreads();

    float s1 = 0.0f, s2 = 0.0f;
#pragma unroll
    for (int i = 0; i < 8; i++) {
        v1[i] = __expf(v1[i] - m1);
        v2[i] = __expf(v2[i] - m2);
        s1 += v1[i];
        s2 += v2[i];
    }
    float l1 = block_reduce(s1, red, false);
    __syncthreads();
    float l2 = block_reduce(s2, red, false);

    const float c1 = 1.0f / l1;
    const float c2 = g_lambda / l2;

    float o[8];
#pragma unroll
    for (int i = 0; i < 8; i++) o[i] = v1[i] * c1 - v2[i] * c2;

    ((float4*)r1)[2 * tid]     = make_float4(o[0], o[1], o[2], o[3]);
    ((float4*)r1)[2 * tid + 1] = make_float4(o[4], o[5], o[6], o[7]);
}

// ---------------------------------------------------------------------------
// GroupNorm over 128 channels per (token, head), then *(1 - LAMBDA_INIT).
// One warp per (s, h).  In-place on g_AO.
// ---------------------------------------------------------------------------
__global__ __launch_bounds__(256)
void groupnorm_kernel(const float* __restrict__ gw, const float* __restrict__ gb)
{
    const int g = (blockIdx.x * blockDim.x + threadIdx.x) >> 5;
    const int lane = threadIdx.x & 31;
    const int s = g >> 4;
    const int h = g & 15;

    float* p = g_AO + (long long)s * DMODEL + h * 128 + lane * 4;
    float4 v = *(float4*)p;
    float sum = v.x + v.y + v.z + v.w;
    float sq  = v.x * v.x + v.y * v.y + v.z * v.z + v.w * v.w;
#pragma unroll
    for (int o = 16; o; o >>= 1) {
        sum += __shfl_xor_sync(0xffffffffu, sum, o);
        sq  += __shfl_xor_sync(0xffffffffu, sq, o);
    }
    const float mean = sum * (1.0f / 128.0f);
    const float var  = sq * (1.0f / 128.0f) - mean * mean;
    const float inv  = rsqrtf(var + 1e-5f);

    const int c = h * 128 + lane * 4;
    float4 w4 = *(const float4*)(gw + c);
    float4 b4 = *(const float4*)(gb + c);
    const float post = 1.0f - LAMBDA_INIT;

    v.x = ((v.x - mean) * inv * w4.x + b4.x) * post;
    v.y = ((v.y - mean) * inv * w4.y + b4.y) * post;
    v.z = ((v.z - mean) * inv * w4.z + b4.z) * post;
    v.w = ((v.w - mean) * inv * w4.w + b4.w) * post;
    *(float4*)p = v;
}

// ---------------------------------------------------------------------------
// Host launch
// ---------------------------------------------------------------------------
extern "C" void kernel_launch(void* const* d_in, const int* in_sizes, int n_in,
                              void* d_out, int out_size)
{
    (void)in_sizes; (void)n_in; (void)out_size;

    const float* x   = (const float*)d_in[0];
    const float* Wq  = (const float*)d_in[1];
    const float* Wk  = (const float*)d_in[2];
    const float* Wv  = (const float*)d_in[3];
    const float* Wo  = (const float*)d_in[4];
    const float* lq1 = (const float*)d_in[5];
    const float* lk1 = (const float*)d_in[6];
    const float* lq2 = (const float*)d_in[7];
    const float* lk2 = (const float*)d_in[8];
    const float* gnw = (const float*)d_in[9];
    const float* gnb = (const float*)d_in[10];
    float* out = (float*)d_out;

    float *pQ, *pK, *pV, *pS, *pAO;
    cudaGetSymbolAddress((void**)&pQ,  g_Q);
    cudaGetSymbolAddress((void**)&pK,  g_K);
    cudaGetSymbolAddress((void**)&pV,  g_V);
    cudaGetSymbolAddress((void**)&pS,  g_S);
    cudaGetSymbolAddress((void**)&pAO, g_AO);

    const dim3 blk(256);
    const dim3 g16(16, 16, 1);

    // Q/K/V projections: [2048,2048] @ [2048,2048]
    gemm_tile128<<<g16, blk>>>(x, DMODEL, 0, Wq, DMODEL, 0, pQ, DMODEL, 0, DMODEL);
    gemm_tile128<<<g16, blk>>>(x, DMODEL, 0, Wk, DMODEL, 0, pK, DMODEL, 0, DMODEL);
    gemm_tile128<<<g16, blk>>>(x, DMODEL, 0, Wv, DMODEL, 0, pV, DMODEL, 0, DMODEL);

    lambda_kernel<<<1, 32>>>(lq1, lk1, lq2, lk2);

    // Scores for all 16 heads x 2 variants
    qk_kernel<<<dim3(16, 16, 32), blk>>>();

    // Softmax both variants + combine into P (in-place, variant-0 slot)
    softmax_combine_kernel<<<dim3(SEQ, NHEAD), blk>>>();

    // P @ V per head:  [2048,2048] @ [2048,128] -> AO[s][h*128+d]
    gemm_tile128<<<dim3(1, 16, NHEAD), blk>>>(pS, SEQ, 2ll * SMAT,
                                              pV, DMODEL, 128,
                                              pAO, DMODEL, 128, SEQ);

    // GroupNorm + (1 - lambda_init)
    groupnorm_kernel<<<(SEQ * NHEAD) / 8, blk>>>(gnw, gnb);

    // Output projection into d_out
    gemm_tile128<<<g16, blk>>>(pAO, DMODEL, 0, Wo, DMODEL, 0, out, DMODEL, 0, DMODEL);
}

// round 5
// speedup vs baseline: 2.2603x; 2.2603x over previous
#include <cuda_runtime.h>
#include <cuda_bf16.h>

#define SEQ     2048
#define DM      2048
#define NHEAD   16
#define LAMBDA_INIT 0.8f
#define NELEM   (SEQ * DM)              // 4194304

typedef unsigned int u32;
typedef unsigned long long u64;

static const long long SMAT = (long long)SEQ * SEQ;

// ---------------- device scratch (no allocations) ----------------
__device__ float g_Q[NELEM], g_K[NELEM], g_V[NELEM], g_AO[NELEM];
__device__ float g_S[32ll * SEQ * SEQ];                       // fp32 scores, 512 MB
__device__ __nv_bfloat16 g_Xh[NELEM],  g_Xl[NELEM];
__device__ __nv_bfloat16 g_WTh[4][NELEM], g_WTl[4][NELEM];    // WqT,WkT,WvT,WoT
__device__ __nv_bfloat16 g_Qh[NELEM],  g_Ql[NELEM];
__device__ __nv_bfloat16 g_Kh[NELEM],  g_Kl[NELEM];
__device__ __nv_bfloat16 g_VTh[NELEM], g_VTl[NELEM];
__device__ __nv_bfloat16 g_Ph[16ll * SEQ * SEQ], g_Pl[16ll * SEQ * SEQ];
__device__ __nv_bfloat16 g_AOh[NELEM], g_AOl[NELEM];
__device__ float g_lambda;

// ---------------- PTX helpers (portable: sm_80+ instructions only) ----------
__device__ __forceinline__ u32 smem_u32(const void* p) {
    u32 a;
    asm("{ .reg .u64 t; cvta.to.shared.u64 t, %1; cvt.u32.u64 %0, t; }" : "=r"(a) : "l"(p));
    return a;
}

#define CP16(saddr, gptr) \
    asm volatile("cp.async.cg.shared.global [%0], [%1], 16;" :: "r"((u32)(saddr)), "l"(gptr))
#define CP_COMMIT() asm volatile("cp.async.commit_group;" ::: "memory")
#define CP_WAIT0()  asm volatile("cp.async.wait_group 0;" ::: "memory")
#define CP_WAIT1()  asm volatile("cp.async.wait_group 1;" ::: "memory")

#define LDSM4(d, addr) \
    asm volatile("ldmatrix.sync.aligned.m8n8.x4.shared.b16 {%0,%1,%2,%3}, [%4];" \
        : "=r"((d)[0]), "=r"((d)[1]), "=r"((d)[2]), "=r"((d)[3]) : "r"((u32)(addr)))
#define LDSM2(d0, d1, addr) \
    asm volatile("ldmatrix.sync.aligned.m8n8.x2.shared.b16 {%0,%1}, [%2];" \
        : "=r"(d0), "=r"(d1) : "r"((u32)(addr)))

#define MMA(acc, a, b0, b1) \
    asm volatile("mma.sync.aligned.m16n8k16.row.col.f32.bf16.bf16.f32 " \
        "{%0,%1,%2,%3}, {%4,%5,%6,%7}, {%8,%9}, {%0,%1,%2,%3};" \
        : "+f"((acc)[0]), "+f"((acc)[1]), "+f"((acc)[2]), "+f"((acc)[3]) \
        : "r"((a)[0]), "r"((a)[1]), "r"((a)[2]), "r"((a)[3]), "r"(b0), "r"(b1))

// ---------------------------------------------------------------------------
// HMMA GEMM with bf16 2-term split (3 MMAs per logical MMA, fp32 accum).
// C[m][n] = sum_k A[m][k]*B[n][k]   (A row-major MxK, B row-major NxK).
// Block tile 128x128, K-chunk 32, 2-stage cp.async pipeline.
// Smem per stage: 4 tiles (Ah, Al, Bh, Bl) of 128 rows x 80B (32 bf16 + pad).
// ---------------------------------------------------------------------------
#define TSTRIDE 80
#define TILEB   (128 * TSTRIDE)            // 10240
#define STAGEB  (4 * TILEB)                // 40960
#define OFF_AH  0
#define OFF_AL  TILEB
#define OFF_BH  (2 * TILEB)
#define OFF_BL  (3 * TILEB)

#define LOAD_CHUNK(ck, st) do {                                               \
    const u32 s0 = sRow + (u32)(st) * STAGEB;                                 \
    const long long kg = (long long)(ck) * 32;                                \
    CP16(s0 + OFF_AH,      gAh + kg);  CP16(s0 + OFF_AH + 16, gAh + kg + 8);  \
    CP16(s0 + OFF_AL,      gAl + kg);  CP16(s0 + OFF_AL + 16, gAl + kg + 8);  \
    CP16(s0 + OFF_BH,      gBh + kg);  CP16(s0 + OFF_BH + 16, gBh + kg + 8);  \
    CP16(s0 + OFF_BL,      gBl + kg);  CP16(s0 + OFF_BL + 16, gBl + kg + 8);  \
} while (0)

__global__ __launch_bounds__(256, 2)
void gemm_mma(const __nv_bfloat16* __restrict__ Ahi, const __nv_bfloat16* __restrict__ Alo,
              long long aBatch, int lda,
              const __nv_bfloat16* __restrict__ Bhi, const __nv_bfloat16* __restrict__ Blo,
              long long bBatch, int ldb,
              float* __restrict__ C, long long cBatch, int ldc, int K)
{
    extern __shared__ char smem[];
    const u32 sb = smem_u32(smem);

    const int tid = threadIdx.x;
    const int wid = tid >> 5;
    const int lid = tid & 31;

    Ahi += blockIdx.z * aBatch;  Alo += blockIdx.z * aBatch;
    Bhi += blockIdx.z * bBatch;  Blo += blockIdx.z * bBatch;
    C   += blockIdx.z * cBatch;
    const int row0 = blockIdx.y * 128;
    const int col0 = blockIdx.x * 128;

    // warp tile: m64 x n32.  2 m-warps x 4 n-warps.
    const int wm0 = (wid & 1) * 64;
    const int wn0 = (wid >> 1) * 32;

    // --- global->smem loader mapping (each thread: 2x uint4 per tile) ---
    const int lr = tid >> 1;            // 0..127 (tile row)
    const int lq = tid & 1;             // which half of the 64B row
    const __nv_bfloat16* gAh = Ahi + (long long)(row0 + lr) * lda + lq * 16;
    const __nv_bfloat16* gAl = Alo + (long long)(row0 + lr) * lda + lq * 16;
    const __nv_bfloat16* gBh = Bhi + (long long)(col0 + lr) * ldb + lq * 16;
    const __nv_bfloat16* gBl = Blo + (long long)(col0 + lr) * ldb + lq * 16;
    const u32 sRow = sb + (u32)(lr * TSTRIDE + lq * 32);

    // --- ldmatrix per-lane offsets ---
    const int r8  = lid & 7;
    const int seg = lid >> 3;           // 0..3
    // A x4: mat0 (m0-7,k0-7), mat1 (m8-15,k0-7), mat2 (m0-7,k8-15), mat3 (m8-15,k8-15)
    const u32 aLane = (u32)(((seg & 1) * 8 + r8) * TSTRIDE + (seg >> 1) * 16);
    // B x2: mat0 (n0-7,k0-7), mat1 (n0-7,k8-15)
    const u32 bLane = (u32)(r8 * TSTRIDE + (seg & 1) * 16);

    float acc[4][4][4];
#pragma unroll
    for (int mi = 0; mi < 4; mi++)
#pragma unroll
        for (int ni = 0; ni < 4; ni++)
#pragma unroll
            for (int q = 0; q < 4; q++) acc[mi][ni][q] = 0.0f;

    const int nch = K >> 5;

    LOAD_CHUNK(0, 0);
    CP_COMMIT();

    for (int ck = 0; ck < nch; ck++) {
        if (ck + 1 < nch) {
            LOAD_CHUNK(ck + 1, (ck + 1) & 1);
            CP_COMMIT();
            CP_WAIT1();
        } else {
            CP_WAIT0();
        }
        __syncthreads();

        const u32 stg   = sb + (u32)((ck & 1) * STAGEB);
        const u32 aBase = stg + (u32)(wm0 * TSTRIDE) + aLane;
        const u32 bBase = stg + (u32)(wn0 * TSTRIDE) + bLane;

#pragma unroll
        for (int ks = 0; ks < 2; ks++) {
            const u32 kb = (u32)(ks * 32);
#pragma unroll
            for (int term = 0; term < 3; term++) {
                const u32 aOff = (term == 1) ? (u32)OFF_AL : (u32)OFF_AH;
                const u32 bOff = (term == 2) ? (u32)OFF_BL : (u32)OFF_BH;
                u32 a[4][4];
#pragma unroll
                for (int mi = 0; mi < 4; mi++)
                    LDSM4(a[mi], aBase + aOff + kb + (u32)(mi * 16 * TSTRIDE));
#pragma unroll
                for (int ni = 0; ni < 4; ni++) {
                    u32 b0, b1;
                    LDSM2(b0, b1, bBase + bOff + kb + (u32)(ni * 8 * TSTRIDE));
#pragma unroll
                    for (int mi = 0; mi < 4; mi++)
                        MMA(acc[mi][ni], a[mi], b0, b1);
                }
            }
        }
        __syncthreads();
    }

    // --- epilogue: fp32 writes, float2 per fragment half ---
    const int rb = row0 + wm0 + (lid >> 2);
    const int cb = col0 + wn0 + (lid & 3) * 2;
#pragma unroll
    for (int mi = 0; mi < 4; mi++) {
#pragma unroll
        for (int ni = 0; ni < 4; ni++) {
            float* p0 = C + (long long)(rb + mi * 16) * ldc + cb + ni * 8;
            float* p1 = p0 + 8ll * ldc;
            *(float2*)p0 = make_float2(acc[mi][ni][0], acc[mi][ni][1]);
            *(float2*)p1 = make_float2(acc[mi][ni][2], acc[mi][ni][3]);
        }
    }
}

// ---------------------------------------------------------------------------
// fp32 -> bf16 hi/lo split (optional scale), elementwise
// ---------------------------------------------------------------------------
__device__ __forceinline__ void bsplit(float v, __nv_bfloat16& h, __nv_bfloat16& l) {
    h = __float2bfloat16(v);
    l = __float2bfloat16(v - __bfloat162float(h));
}

__global__ __launch_bounds__(256)
void split_kernel(const float* __restrict__ src, __nv_bfloat16* __restrict__ dh,
                  __nv_bfloat16* __restrict__ dl, float scale)
{
    const int i = (blockIdx.x * blockDim.x + threadIdx.x) * 4;
    float4 v = *(const float4*)(src + i);
    __nv_bfloat16 h[4], l[4];
    bsplit(v.x * scale, h[0], l[0]);
    bsplit(v.y * scale, h[1], l[1]);
    bsplit(v.z * scale, h[2], l[2]);
    bsplit(v.w * scale, h[3], l[3]);
    *(uint2*)(dh + i) = *(uint2*)h;
    *(uint2*)(dl + i) = *(uint2*)l;
}

// fp32 [2048][2048] -> transposed bf16 hi/lo [2048][2048]
__global__ __launch_bounds__(256)
void splitT_kernel(const float* __restrict__ src, __nv_bfloat16* __restrict__ dh,
                   __nv_bfloat16* __restrict__ dl)
{
    __shared__ float tile[32][33];
    const int bx = blockIdx.x * 32;   // src col base
    const int by = blockIdx.y * 32;   // src row base
    const int tx = threadIdx.x, ty = threadIdx.y;
#pragma unroll
    for (int i = 0; i < 32; i += 8)
        tile[ty + i][tx] = src[(long long)(by + ty + i) * DM + bx + tx];
    __syncthreads();
#pragma unroll
    for (int i = 0; i < 32; i += 8) {
        float v = tile[tx][ty + i];   // = src[by+tx][bx+ty+i]
        __nv_bfloat16 h, l;
        bsplit(v, h, l);
        const long long o = (long long)(bx + ty + i) * DM + by + tx;
        dh[o] = h;
        dl[o] = l;
    }
}

// ---------------------------------------------------------------------------
// lambda = exp(sum(lq1*lk1)) - exp(sum(lq2*lk2)) + 0.8
// ---------------------------------------------------------------------------
__global__ void lambda_kernel(const float* __restrict__ lq1, const float* __restrict__ lk1,
                              const float* __restrict__ lq2, const float* __restrict__ lk2)
{
    if (threadIdx.x == 0) {
        float s1 = 0.0f, s2 = 0.0f;
        for (int i = 0; i < 64; i++) { s1 += lq1[i] * lk1[i]; s2 += lq2[i] * lk2[i]; }
        g_lambda = expf(s1) - expf(s2) + LAMBDA_INIT;
    }
}

// ---------------------------------------------------------------------------
// Softmax both variants + combine P = p1 - lam*p2, writing P as bf16 hi/lo
// ---------------------------------------------------------------------------
__device__ __forceinline__ float block_red(float v, float* red, bool ismax)
{
#pragma unroll
    for (int o = 16; o; o >>= 1) {
        float ov = __shfl_xor_sync(0xffffffffu, v, o);
        v = ismax ? fmaxf(v, ov) : (v + ov);
    }
    __syncthreads();
    if ((threadIdx.x & 31) == 0) red[threadIdx.x >> 5] = v;
    __syncthreads();
    float r = red[0];
#pragma unroll
    for (int i = 1; i < 8; i++) r = ismax ? fmaxf(r, red[i]) : (r + red[i]);
    return r;
}

__global__ __launch_bounds__(256)
void softmax_combine_kernel()
{
    const int s = blockIdx.x;
    const int h = blockIdx.y;
    const int tid = threadIdx.x;

    const float* __restrict__ r1 = g_S + (long long)(2 * h) * SMAT + (long long)s * SEQ;
    const float* __restrict__ r2 = r1 + SMAT;

    __shared__ float red[8];

    float4 a0 = ((const float4*)r1)[2 * tid];
    float4 a1 = ((const float4*)r1)[2 * tid + 1];
    float4 b0 = ((const float4*)r2)[2 * tid];
    float4 b1 = ((const float4*)r2)[2 * tid + 1];
    float v1[8] = {a0.x, a0.y, a0.z, a0.w, a1.x, a1.y, a1.z, a1.w};
    float v2[8] = {b0.x, b0.y, b0.z, b0.w, b1.x, b1.y, b1.z, b1.w};

    float m1 = -1e30f, m2 = -1e30f;
#pragma unroll
    for (int i = 0; i < 8; i++) { m1 = fmaxf(m1, v1[i]); m2 = fmaxf(m2, v2[i]); }
    m1 = block_red(m1, red, true);
    __syncthreads();
    m2 = block_red(m2, red, true);
    __syncthreads();

    float s1 = 0.0f, s2 = 0.0f;
#pragma unroll
    for (int i = 0; i < 8; i++) {
        v1[i] = __expf(v1[i] - m1);
        v2[i] = __expf(v2[i] - m2);
        s1 += v1[i];
        s2 += v2[i];
    }
    float l1 = block_red(s1, red, false);
    __syncthreads();
    float l2 = block_red(s2, red, false);

    const float c1 = 1.0f / l1;
    const float c2 = g_lambda / l2;

    __nv_bfloat16 oh[8], ol[8];
#pragma unroll
    for (int i = 0; i < 8; i++) {
        float o = v1[i] * c1 - v2[i] * c2;
        bsplit(o, oh[i], ol[i]);
    }
    const long long off = (long long)h * SMAT + (long long)s * SEQ + tid * 8;
    *(uint4*)(g_Ph + off) = *(uint4*)oh;
    *(uint4*)(g_Pl + off) = *(uint4*)ol;
}

// ---------------------------------------------------------------------------
// GroupNorm over 128 channels per (token, head), then *(1 - LAMBDA_INIT)
// ---------------------------------------------------------------------------
__global__ __launch_bounds__(256)
void groupnorm_kernel(const float* __restrict__ gw, const float* __restrict__ gb)
{
    const int g = (blockIdx.x * blockDim.x + threadIdx.x) >> 5;
    const int lane = threadIdx.x & 31;
    const int s = g >> 4;
    const int h = g & 15;

    float* p = g_AO + (long long)s * DM + h * 128 + lane * 4;
    float4 v = *(float4*)p;
    float sum = v.x + v.y + v.z + v.w;
    float sq  = v.x * v.x + v.y * v.y + v.z * v.z + v.w * v.w;
#pragma unroll
    for (int o = 16; o; o >>= 1) {
        sum += __shfl_xor_sync(0xffffffffu, sum, o);
        sq  += __shfl_xor_sync(0xffffffffu, sq, o);
    }
    const float mean = sum * (1.0f / 128.0f);
    const float var  = sq * (1.0f / 128.0f) - mean * mean;
    const float inv  = rsqrtf(var + 1e-5f);

    const int c = h * 128 + lane * 4;
    float4 w4 = *(const float4*)(gw + c);
    float4 b4 = *(const float4*)(gb + c);
    const float post = 1.0f - LAMBDA_INIT;

    v.x = ((v.x - mean) * inv * w4.x + b4.x) * post;
    v.y = ((v.y - mean) * inv * w4.y + b4.y) * post;
    v.z = ((v.z - mean) * inv * w4.z + b4.z) * post;
    v.w = ((v.w - mean) * inv * w4.w + b4.w) * post;
    *(float4*)p = v;
}

// ---------------------------------------------------------------------------
// Host launch
// ---------------------------------------------------------------------------
extern "C" void kernel_launch(void* const* d_in, const int* in_sizes, int n_in,
                              void* d_out, int out_size)
{
    (void)in_sizes; (void)n_in; (void)out_size;

    const float* x   = (const float*)d_in[0];
    const float* Wq  = (const float*)d_in[1];
    const float* Wk  = (const float*)d_in[2];
    const float* Wv  = (const float*)d_in[3];
    const float* Wo  = (const float*)d_in[4];
    const float* lq1 = (const float*)d_in[5];
    const float* lk1 = (const float*)d_in[6];
    const float* lq2 = (const float*)d_in[7];
    const float* lk2 = (const float*)d_in[8];
    const float* gnw = (const float*)d_in[9];
    const float* gnb = (const float*)d_in[10];
    float* out = (float*)d_out;

    float *pQ, *pK, *pV, *pS, *pAO;
    __nv_bfloat16 *pXh, *pXl, *pWTh, *pWTl, *pQh, *pQl, *pKh, *pKl;
    __nv_bfloat16 *pVTh, *pVTl, *pPh, *pPl, *pAOh, *pAOl;
    cudaGetSymbolAddress((void**)&pQ,   g_Q);
    cudaGetSymbolAddress((void**)&pK,   g_K);
    cudaGetSymbolAddress((void**)&pV,   g_V);
    cudaGetSymbolAddress((void**)&pS,   g_S);
    cudaGetSymbolAddress((void**)&pAO,  g_AO);
    cudaGetSymbolAddress((void**)&pXh,  g_Xh);
    cudaGetSymbolAddress((void**)&pXl,  g_Xl);
    cudaGetSymbolAddress((void**)&pWTh, g_WTh);
    cudaGetSymbolAddress((void**)&pWTl, g_WTl);
    cudaGetSymbolAddress((void**)&pQh,  g_Qh);
    cudaGetSymbolAddress((void**)&pQl,  g_Ql);
    cudaGetSymbolAddress((void**)&pKh,  g_Kh);
    cudaGetSymbolAddress((void**)&pKl,  g_Kl);
    cudaGetSymbolAddress((void**)&pVTh, g_VTh);
    cudaGetSymbolAddress((void**)&pVTl, g_VTl);
    cudaGetSymbolAddress((void**)&pPh,  g_Ph);
    cudaGetSymbolAddress((void**)&pPl,  g_Pl);
    cudaGetSymbolAddress((void**)&pAOh, g_AOh);
    cudaGetSymbolAddress((void**)&pAOl, g_AOl);

    const int GSMEM = 2 * STAGEB;   // 81920
    cudaFuncSetAttribute(gemm_mma, cudaFuncAttributeMaxDynamicSharedMemorySize, GSMEM);

    const dim3 blk(256);
    const dim3 tblk(32, 8);

    // --- input conversions ---
    split_kernel<<<NELEM / 1024, blk>>>(x, pXh, pXl, 1.0f);
    splitT_kernel<<<dim3(64, 64), tblk>>>(Wq, pWTh + 0ll * NELEM, pWTl + 0ll * NELEM);
    splitT_kernel<<<dim3(64, 64), tblk>>>(Wk, pWTh + 1ll * NELEM, pWTl + 1ll * NELEM);
    splitT_kernel<<<dim3(64, 64), tblk>>>(Wv, pWTh + 2ll * NELEM, pWTl + 2ll * NELEM);
    splitT_kernel<<<dim3(64, 64), tblk>>>(Wo, pWTh + 3ll * NELEM, pWTl + 3ll * NELEM);

    // --- QKV projections ---
    gemm_mma<<<dim3(16, 16, 1), blk, GSMEM>>>(pXh, pXl, 0, DM,
        pWTh + 0ll * NELEM, pWTl + 0ll * NELEM, 0, DM, pQ, 0, DM, DM);
    gemm_mma<<<dim3(16, 16, 1), blk, GSMEM>>>(pXh, pXl, 0, DM,
        pWTh + 1ll * NELEM, pWTl + 1ll * NELEM, 0, DM, pK, 0, DM, DM);
    gemm_mma<<<dim3(16, 16, 1), blk, GSMEM>>>(pXh, pXl, 0, DM,
        pWTh + 2ll * NELEM, pWTl + 2ll * NELEM, 0, DM, pV, 0, DM, DM);

    // --- mid conversions (Q scaled by 1/sqrt(64)) ---
    split_kernel<<<NELEM / 1024, blk>>>(pQ, pQh, pQl, 0.125f);
    split_kernel<<<NELEM / 1024, blk>>>(pK, pKh, pKl, 1.0f);
    splitT_kernel<<<dim3(64, 64), tblk>>>(pV, pVTh, pVTl);

    lambda_kernel<<<1, 32>>>(lq1, lk1, lq2, lk2);

    // --- QK^T: z = head*2+variant, slice offset z*64, K=64 ---
    gemm_mma<<<dim3(16, 16, 32), blk, GSMEM>>>(pQh, pQl, 64, DM,
        pKh, pKl, 64, DM, pS, SMAT, SEQ, 64);

    // --- softmax both variants + combine -> P (bf16 hi/lo) ---
    softmax_combine_kernel<<<dim3(SEQ, NHEAD), blk>>>();

    // --- P @ V per head: z = head, N = 128 channels ---
    gemm_mma<<<dim3(1, 16, 16), blk, GSMEM>>>(pPh, pPl, SMAT, SEQ,
        pVTh, pVTl, 128ll * DM, SEQ, pAO, 128, DM, SEQ);

    // --- GroupNorm + (1 - lambda_init) ---
    groupnorm_kernel<<<(SEQ * NHEAD) / 8, blk>>>(gnw, gnb);

    // --- output projection ---
    split_kernel<<<NELEM / 1024, blk>>>(pAO, pAOh, pAOl, 1.0f);
    gemm_mma<<<dim3(16, 16, 1), blk, GSMEM>>>(pAOh, pAOl, 0, DM,
        pWTh + 3ll * NELEM, pWTl + 3ll * NELEM, 0, DM, out, 0, DM, DM);
}

// round 6
// speedup vs baseline: 3.3208x; 1.4692x over previous
#include <cuda_runtime.h>
#include <cuda_fp16.h>

#define SEQ     2048
#define DM      2048
#define NHEAD   16
#define LAMBDA_INIT 0.8f
#define NELEM   (SEQ * DM)              // 4194304

typedef unsigned int u32;
typedef unsigned long long u64;

static const long long SMAT = (long long)SEQ * SEQ;

// ---------------- device scratch (no allocations) ----------------
__device__ float  g_V[NELEM], g_AO[NELEM];
__device__ __half s_Xh[NELEM], s_Xl[NELEM];
__device__ __half s_WT[4][NELEM];                 // WqT,WkT,WvT,WoT (single fp16)
__device__ __half s_Qf[NELEM], s_Kf[NELEM];       // fp16, Q pre-scaled by 1/8
__device__ __half s_VT[NELEM];                    // V transposed [c][t]
__device__ __half s_S[32ll * SEQ * SEQ];          // fp16 scores, 256 MB
__device__ __half s_P[16ll * SEQ * SEQ];          // combined P, fp16, 128 MB
__device__ __half s_AOh[NELEM], s_AOl[NELEM];
__device__ float g_lambda;

// ---------------- PTX helpers (sm_80+ portable) ----------------
__device__ __forceinline__ u32 smem_u32(const void* p) {
    u32 a;
    asm("{ .reg .u64 t; cvta.to.shared.u64 t, %1; cvt.u32.u64 %0, t; }" : "=r"(a) : "l"(p));
    return a;
}

#define CP16(saddr, gptr) \
    asm volatile("cp.async.cg.shared.global [%0], [%1], 16;" :: "r"((u32)(saddr)), "l"(gptr))
#define CP_COMMIT() asm volatile("cp.async.commit_group;" ::: "memory")
#define CP_WAIT0()  asm volatile("cp.async.wait_group 0;" ::: "memory")
#define CP_WAIT1()  asm volatile("cp.async.wait_group 1;" ::: "memory")

#define LDSM4(d, addr) \
    asm volatile("ldmatrix.sync.aligned.m8n8.x4.shared.b16 {%0,%1,%2,%3}, [%4];" \
        : "=r"((d)[0]), "=r"((d)[1]), "=r"((d)[2]), "=r"((d)[3]) : "r"((u32)(addr)))
#define LDSM2(d0, d1, addr) \
    asm volatile("ldmatrix.sync.aligned.m8n8.x2.shared.b16 {%0,%1}, [%2];" \
        : "=r"(d0), "=r"(d1) : "r"((u32)(addr)))

#define MMAH(acc, a, b0, b1) \
    asm volatile("mma.sync.aligned.m16n8k16.row.col.f32.f16.f16.f32 " \
        "{%0,%1,%2,%3}, {%4,%5,%6,%7}, {%8,%9}, {%0,%1,%2,%3};" \
        : "+f"((acc)[0]), "+f"((acc)[1]), "+f"((acc)[2]), "+f"((acc)[3]) \
        : "r"((a)[0]), "r"((a)[1]), "r"((a)[2]), "r"((a)[3]), "r"(b0), "r"(b1))

// ---------------------------------------------------------------------------
// fp16 HMMA GEMM.  C[m][n] = cs * sum_k A[m][k]*B[n][k]
// A = Ah (+ Al if TERMS==2, error-compensated split); B single fp16.
// Block tile 128x128, K-chunk 32, 2-stage cp.async pipeline.
// Smem/stage: (TERMS+1) tiles of 128 rows x 80 B (32 halfs + pad).
// ---------------------------------------------------------------------------
#define TSTRIDE 80
#define TILEB   (128 * TSTRIDE)            // 10240

template<int TERMS, typename CT>
__global__ __launch_bounds__(256, 2)
void gemm_f16(const __half* __restrict__ Ah, const __half* __restrict__ Al,
              long long aBatch, int lda,
              const __half* __restrict__ B, long long bBatch, int ldb,
              CT* __restrict__ C, long long cBatch, int ldc, int K, float cs)
{
    constexpr int NT     = TERMS + 1;        // tiles per stage
    constexpr int STAGEB = NT * TILEB;
    constexpr int OFF_B  = TERMS * TILEB;

    extern __shared__ char smem[];
    const u32 sb = smem_u32(smem);

    const int tid = threadIdx.x;
    const int wid = tid >> 5;
    const int lid = tid & 31;

    Ah += blockIdx.z * aBatch;
    Al += blockIdx.z * aBatch;
    B  += blockIdx.z * bBatch;
    C  += blockIdx.z * cBatch;
    const int row0 = blockIdx.y * 128;
    const int col0 = blockIdx.x * 128;

    const int wm0 = (wid & 1) * 64;
    const int wn0 = (wid >> 1) * 32;

    // loader: each thread 2x16B per tile
    const int lr = tid >> 1;
    const int lq = tid & 1;
    const __half* gAh = Ah + (long long)(row0 + lr) * lda + lq * 16;
    const __half* gAl = Al + (long long)(row0 + lr) * lda + lq * 16;
    const __half* gB  = B  + (long long)(col0 + lr) * ldb + lq * 16;
    const u32 sRow = sb + (u32)(lr * TSTRIDE + lq * 32);

    // ldmatrix per-lane offsets
    const int r8  = lid & 7;
    const int seg = lid >> 3;
    const u32 aLane = (u32)(((seg & 1) * 8 + r8) * TSTRIDE + (seg >> 1) * 16);
    const u32 bLane = (u32)(r8 * TSTRIDE + (seg & 1) * 16);

    float acc[4][4][4];
#pragma unroll
    for (int mi = 0; mi < 4; mi++)
#pragma unroll
        for (int ni = 0; ni < 4; ni++)
#pragma unroll
            for (int q = 0; q < 4; q++) acc[mi][ni][q] = 0.0f;

    const int nch = K >> 5;

#define LOADC(ck, st) do {                                                    \
        const u32 s0 = sRow + (u32)(st) * STAGEB;                             \
        const long long kg = (long long)(ck) * 32;                            \
        CP16(s0, gAh + kg);  CP16(s0 + 16, gAh + kg + 8);                     \
        if (TERMS == 2) { CP16(s0 + TILEB, gAl + kg);                         \
                          CP16(s0 + TILEB + 16, gAl + kg + 8); }              \
        CP16(s0 + OFF_B, gB + kg);  CP16(s0 + OFF_B + 16, gB + kg + 8);       \
    } while (0)

    LOADC(0, 0);
    CP_COMMIT();

    for (int ck = 0; ck < nch; ck++) {
        if (ck + 1 < nch) {
            LOADC(ck + 1, (ck + 1) & 1);
            CP_COMMIT();
            CP_WAIT1();
        } else {
            CP_WAIT0();
        }
        __syncthreads();

        const u32 stg   = sb + (u32)((ck & 1) * STAGEB);
        const u32 aBase = stg + (u32)(wm0 * TSTRIDE) + aLane;
        const u32 bBase = stg + (u32)(OFF_B + wn0 * TSTRIDE) + bLane;

#pragma unroll
        for (int ks = 0; ks < 2; ks++) {
            const u32 kb = (u32)(ks * 32);
            u32 b0[4], b1[4];
#pragma unroll
            for (int ni = 0; ni < 4; ni++)
                LDSM2(b0[ni], b1[ni], bBase + kb + (u32)(ni * 8 * TSTRIDE));
#pragma unroll
            for (int t = 0; t < TERMS; t++) {
                u32 a[4][4];
#pragma unroll
                for (int mi = 0; mi < 4; mi++)
                    LDSM4(a[mi], aBase + (u32)(t * TILEB) + kb + (u32)(mi * 16 * TSTRIDE));
#pragma unroll
                for (int ni = 0; ni < 4; ni++)
#pragma unroll
                    for (int mi = 0; mi < 4; mi++)
                        MMAH(acc[mi][ni], a[mi], b0[ni], b1[ni]);
            }
        }
        __syncthreads();
    }
#undef LOADC

    // epilogue
    const int rb = row0 + wm0 + (lid >> 2);
    const int cb = col0 + wn0 + (lid & 3) * 2;
#pragma unroll
    for (int mi = 0; mi < 4; mi++) {
#pragma unroll
        for (int ni = 0; ni < 4; ni++) {
            CT* p0 = C + (long long)(rb + mi * 16) * ldc + cb + ni * 8;
            CT* p1 = p0 + 8ll * ldc;
            if (sizeof(CT) == 2) {
                *(__half2*)p0 = __floats2half2_rn(acc[mi][ni][0] * cs, acc[mi][ni][1] * cs);
                *(__half2*)p1 = __floats2half2_rn(acc[mi][ni][2] * cs, acc[mi][ni][3] * cs);
            } else {
                *(float2*)p0 = make_float2(acc[mi][ni][0] * cs, acc[mi][ni][1] * cs);
                *(float2*)p1 = make_float2(acc[mi][ni][2] * cs, acc[mi][ni][3] * cs);
            }
        }
    }
}

// ---------------------------------------------------------------------------
// fp32 -> fp16 hi/lo split (elementwise)
// ---------------------------------------------------------------------------
__device__ __forceinline__ void hsplit(float v, __half& h, __half& l) {
    h = __float2half_rn(v);
    l = __float2half_rn(v - __half2float(h));
}

__global__ __launch_bounds__(256)
void split_kernel(const float* __restrict__ src, __half* __restrict__ dh,
                  __half* __restrict__ dl)
{
    const int i = (blockIdx.x * blockDim.x + threadIdx.x) * 4;
    float4 v = *(const float4*)(src + i);
    __half h[4], l[4];
    hsplit(v.x, h[0], l[0]);
    hsplit(v.y, h[1], l[1]);
    hsplit(v.z, h[2], l[2]);
    hsplit(v.w, h[3], l[3]);
    *(uint2*)(dh + i) = *(uint2*)h;
    *(uint2*)(dl + i) = *(uint2*)l;
}

// fp32 [2048][2048] -> transposed single fp16 [2048][2048]
__global__ __launch_bounds__(256)
void convT_kernel(const float* __restrict__ src, __half* __restrict__ dst)
{
    __shared__ float tile[32][33];
    const int bx = blockIdx.x * 32;
    const int by = blockIdx.y * 32;
    const int tx = threadIdx.x, ty = threadIdx.y;
#pragma unroll
    for (int i = 0; i < 32; i += 8)
        tile[ty + i][tx] = src[(long long)(by + ty + i) * DM + bx + tx];
    __syncthreads();
#pragma unroll
    for (int i = 0; i < 32; i += 8)
        dst[(long long)(bx + ty + i) * DM + by + tx] = __float2half_rn(tile[tx][ty + i]);
}

// ---------------------------------------------------------------------------
// lambda = exp(sum(lq1*lk1)) - exp(sum(lq2*lk2)) + 0.8
// ---------------------------------------------------------------------------
__global__ void lambda_kernel(const float* __restrict__ lq1, const float* __restrict__ lk1,
                              const float* __restrict__ lq2, const float* __restrict__ lk2)
{
    if (threadIdx.x == 0) {
        float s1 = 0.0f, s2 = 0.0f;
        for (int i = 0; i < 64; i++) { s1 += lq1[i] * lk1[i]; s2 += lq2[i] * lk2[i]; }
        g_lambda = expf(s1) - expf(s2) + LAMBDA_INIT;
    }
}

// ---------------------------------------------------------------------------
// Softmax both variants (fp16 scores) + combine P = p1/l1 - lam*p2/l2 (fp16)
// ---------------------------------------------------------------------------
__device__ __forceinline__ float block_red(float v, float* red, bool ismax)
{
#pragma unroll
    for (int o = 16; o; o >>= 1) {
        float ov = __shfl_xor_sync(0xffffffffu, v, o);
        v = ismax ? fmaxf(v, ov) : (v + ov);
    }
    __syncthreads();
    if ((threadIdx.x & 31) == 0) red[threadIdx.x >> 5] = v;
    __syncthreads();
    float r = red[0];
#pragma unroll
    for (int i = 1; i < 8; i++) r = ismax ? fmaxf(r, red[i]) : (r + red[i]);
    return r;
}

__global__ __launch_bounds__(256)
void softmax_combine_kernel()
{
    const int s = blockIdx.x;
    const int h = blockIdx.y;
    const int tid = threadIdx.x;

    const __half* __restrict__ r1 = s_S + (long long)(2 * h) * SMAT + (long long)s * SEQ;
    const __half* __restrict__ r2 = r1 + SMAT;

    __shared__ float red[8];

    uint4 w1 = ((const uint4*)r1)[tid];
    uint4 w2 = ((const uint4*)r2)[tid];
    const __half* h1 = (const __half*)&w1;
    const __half* h2 = (const __half*)&w2;
    float v1[8], v2[8];
#pragma unroll
    for (int i = 0; i < 8; i++) { v1[i] = __half2float(h1[i]); v2[i] = __half2float(h2[i]); }

    float m1 = -1e30f, m2 = -1e30f;
#pragma unroll
    for (int i = 0; i < 8; i++) { m1 = fmaxf(m1, v1[i]); m2 = fmaxf(m2, v2[i]); }
    m1 = block_red(m1, red, true);
    __syncthreads();
    m2 = block_red(m2, red, true);
    __syncthreads();

    float s1 = 0.0f, s2 = 0.0f;
#pragma unroll
    for (int i = 0; i < 8; i++) {
        v1[i] = __expf(v1[i] - m1);
        v2[i] = __expf(v2[i] - m2);
        s1 += v1[i];
        s2 += v2[i];
    }
    float l1 = block_red(s1, red, false);
    __syncthreads();
    float l2 = block_red(s2, red, false);

    const float c1 = 1.0f / l1;
    const float c2 = g_lambda / l2;

    __half o[8];
#pragma unroll
    for (int i = 0; i < 8; i++)
        o[i] = __float2half_rn(v1[i] * c1 - v2[i] * c2);
    ((uint4*)(s_P + (long long)h * SMAT + (long long)s * SEQ))[tid] = *(uint4*)o;
}

// ---------------------------------------------------------------------------
// GroupNorm over 128 channels per (token, head), then *(1 - LAMBDA_INIT)
// ---------------------------------------------------------------------------
__global__ __launch_bounds__(256)
void groupnorm_kernel(const float* __restrict__ gw, const float* __restrict__ gb)
{
    const int g = (blockIdx.x * blockDim.x + threadIdx.x) >> 5;
    const int lane = threadIdx.x & 31;
    const int s = g >> 4;
    const int h = g & 15;

    float* p = g_AO + (long long)s * DM + h * 128 + lane * 4;
    float4 v = *(float4*)p;
    float sum = v.x + v.y + v.z + v.w;
    float sq  = v.x * v.x + v.y * v.y + v.z * v.z + v.w * v.w;
#pragma unroll
    for (int o = 16; o; o >>= 1) {
        sum += __shfl_xor_sync(0xffffffffu, sum, o);
        sq  += __shfl_xor_sync(0xffffffffu, sq, o);
    }
    const float mean = sum * (1.0f / 128.0f);
    const float var  = sq * (1.0f / 128.0f) - mean * mean;
    const float inv  = rsqrtf(var + 1e-5f);

    const int c = h * 128 + lane * 4;
    float4 w4 = *(const float4*)(gw + c);
    float4 b4 = *(const float4*)(gb + c);
    const float post = 1.0f - LAMBDA_INIT;

    v.x = ((v.x - mean) * inv * w4.x + b4.x) * post;
    v.y = ((v.y - mean) * inv * w4.y + b4.y) * post;
    v.z = ((v.z - mean) * inv * w4.z + b4.z) * post;
    v.w = ((v.w - mean) * inv * w4.w + b4.w) * post;
    *(float4*)p = v;
}

// ---------------------------------------------------------------------------
// Host launch
// ---------------------------------------------------------------------------
extern "C" void kernel_launch(void* const* d_in, const int* in_sizes, int n_in,
                              void* d_out, int out_size)
{
    (void)in_sizes; (void)n_in; (void)out_size;

    const float* x   = (const float*)d_in[0];
    const float* Wq  = (const float*)d_in[1];
    const float* Wk  = (const float*)d_in[2];
    const float* Wv  = (const float*)d_in[3];
    const float* Wo  = (const float*)d_in[4];
    const float* lq1 = (const float*)d_in[5];
    const float* lk1 = (const float*)d_in[6];
    const float* lq2 = (const float*)d_in[7];
    const float* lk2 = (const float*)d_in[8];
    const float* gnw = (const float*)d_in[9];
    const float* gnb = (const float*)d_in[10];
    float* out = (float*)d_out;

    float *pV, *pAO;
    __half *pXh, *pXl, *pWT, *pQf, *pKf, *pVT, *pS, *pP, *pAOh, *pAOl;
    cudaGetSymbolAddress((void**)&pV,   g_V);
    cudaGetSymbolAddress((void**)&pAO,  g_AO);
    cudaGetSymbolAddress((void**)&pXh,  s_Xh);
    cudaGetSymbolAddress((void**)&pXl,  s_Xl);
    cudaGetSymbolAddress((void**)&pWT,  s_WT);
    cudaGetSymbolAddress((void**)&pQf,  s_Qf);
    cudaGetSymbolAddress((void**)&pKf,  s_Kf);
    cudaGetSymbolAddress((void**)&pVT,  s_VT);
    cudaGetSymbolAddress((void**)&pS,   s_S);
    cudaGetSymbolAddress((void**)&pP,   s_P);
    cudaGetSymbolAddress((void**)&pAOh, s_AOh);
    cudaGetSymbolAddress((void**)&pAOl, s_AOl);

    const int SM2 = 2 * 3 * TILEB;   // 61440 (TERMS=2)
    const int SM1 = 2 * 2 * TILEB;   // 40960 (TERMS=1)
    cudaFuncSetAttribute(gemm_f16<2, __half>, cudaFuncAttributeMaxDynamicSharedMemorySize, SM2);
    cudaFuncSetAttribute(gemm_f16<2, float>,  cudaFuncAttributeMaxDynamicSharedMemorySize, SM2);

    const dim3 blk(256);
    const dim3 tblk(32, 8);

    // --- input conversions ---
    split_kernel<<<NELEM / 1024, blk>>>(x, pXh, pXl);
    convT_kernel<<<dim3(64, 64), tblk>>>(Wq, pWT + 0ll * NELEM);
    convT_kernel<<<dim3(64, 64), tblk>>>(Wk, pWT + 1ll * NELEM);
    convT_kernel<<<dim3(64, 64), tblk>>>(Wv, pWT + 2ll * NELEM);
    convT_kernel<<<dim3(64, 64), tblk>>>(Wo, pWT + 3ll * NELEM);

    // --- QKV projections (2-term split); Q pre-scaled by 1/sqrt(64) ---
    gemm_f16<2, __half><<<dim3(16, 16, 1), blk, SM2>>>(pXh, pXl, 0, DM,
        pWT + 0ll * NELEM, 0, DM, pQf, 0, DM, DM, 0.125f);
    gemm_f16<2, __half><<<dim3(16, 16, 1), blk, SM2>>>(pXh, pXl, 0, DM,
        pWT + 1ll * NELEM, 0, DM, pKf, 0, DM, DM, 1.0f);
    gemm_f16<2, float><<<dim3(16, 16, 1), blk, SM2>>>(pXh, pXl, 0, DM,
        pWT + 2ll * NELEM, 0, DM, pV, 0, DM, DM, 1.0f);

    convT_kernel<<<dim3(64, 64), tblk>>>(pV, pVT);
    lambda_kernel<<<1, 32>>>(lq1, lk1, lq2, lk2);

    // --- QK^T: z = head*2+variant, slice offset z*64, K=64, fp16 scores ---
    gemm_f16<1, __half><<<dim3(16, 16, 32), blk, SM1>>>(pQf, pQf, 64, DM,
        pKf, 64, DM, pS, SMAT, SEQ, 64, 1.0f);

    // --- softmax both variants + combine -> P (single fp16) ---
    softmax_combine_kernel<<<dim3(SEQ, NHEAD), blk>>>();

    // --- P @ V per head: N = 128 channels, K = 2048 ---
    gemm_f16<1, float><<<dim3(1, 16, 16), blk, SM1>>>(pP, pP, SMAT, SEQ,
        pVT, 128ll * SEQ, SEQ, pAO, 128, DM, SEQ, 1.0f);

    // --- GroupNorm + (1 - lambda_init) ---
    groupnorm_kernel<<<(SEQ * NHEAD) / 8, blk>>>(gnw, gnb);

    // --- output projection (2-term split) ---
    split_kernel<<<NELEM / 1024, blk>>>(pAO, pAOh, pAOl);
    gemm_f16<2, float><<<dim3(16, 16, 1), blk, SM2>>>(pAOh, pAOl, 0, DM,
        pWT + 3ll * NELEM, 0, DM, out, 0, DM, DM, 1.0f);
}

// round 7
// speedup vs baseline: 3.7822x; 1.1389x over previous
#include <cuda_runtime.h>
#include <cuda_fp16.h>

#define SEQ     2048
#define DM      2048
#define NHEAD   16
#define LAMBDA_INIT 0.8f
#define NELEM   (SEQ * DM)

typedef unsigned int u32;

// ---------------- device scratch (no allocations) ----------------
__device__ __half s_Xh[NELEM], s_Xl[NELEM];
__device__ __half s_WT[4][NELEM];               // WqT,WkT,WvT,WoT fp16
__device__ __half s_Qf[NELEM];                  // Q fp16, pre-scaled 1/8
__device__ __half s_Kf[NELEM];
__device__ __half s_Vf[NELEM];
__device__ __half s_AOh[NELEM], s_AOl[NELEM];   // attn out hi/lo split
__device__ float g_lambda;

// ---------------- PTX helpers (sm_80+ portable) ----------------
__device__ __forceinline__ u32 smem_u32(const void* p) {
    u32 a;
    asm("{ .reg .u64 t; cvta.to.shared.u64 t, %1; cvt.u32.u64 %0, t; }" : "=r"(a) : "l"(p));
    return a;
}

#define CP16(saddr, gptr) \
    asm volatile("cp.async.cg.shared.global [%0], [%1], 16;" :: "r"((u32)(saddr)), "l"(gptr))
#define CP_COMMIT() asm volatile("cp.async.commit_group;" ::: "memory")
#define CP_WAIT0()  asm volatile("cp.async.wait_group 0;" ::: "memory")
#define CP_WAIT1()  asm volatile("cp.async.wait_group 1;" ::: "memory")

#define LDSM4(d, addr) \
    asm volatile("ldmatrix.sync.aligned.m8n8.x4.shared.b16 {%0,%1,%2,%3}, [%4];" \
        : "=r"((d)[0]), "=r"((d)[1]), "=r"((d)[2]), "=r"((d)[3]) : "r"((u32)(addr)))
#define LDSM4T(d, addr) \
    asm volatile("ldmatrix.sync.aligned.m8n8.x4.trans.shared.b16 {%0,%1,%2,%3}, [%4];" \
        : "=r"((d)[0]), "=r"((d)[1]), "=r"((d)[2]), "=r"((d)[3]) : "r"((u32)(addr)))
#define LDSM2(d0, d1, addr) \
    asm volatile("ldmatrix.sync.aligned.m8n8.x2.shared.b16 {%0,%1}, [%2];" \
        : "=r"(d0), "=r"(d1) : "r"((u32)(addr)))

#define MMAH(acc, a, b0, b1) \
    asm volatile("mma.sync.aligned.m16n8k16.row.col.f32.f16.f16.f32 " \
        "{%0,%1,%2,%3}, {%4,%5,%6,%7}, {%8,%9}, {%0,%1,%2,%3};" \
        : "+f"((acc)[0]), "+f"((acc)[1]), "+f"((acc)[2]), "+f"((acc)[3]) \
        : "r"((a)[0]), "r"((a)[1]), "r"((a)[2]), "r"((a)[3]), "r"(b0), "r"(b1))

__device__ __forceinline__ u32 packh2(float a, float b) {
    __half2 t = __floats2half2_rn(a, b);
    return *(u32*)&t;
}
__device__ __forceinline__ void hsplit(float v, __half& h, __half& l) {
    h = __float2half_rn(v);
    l = __float2half_rn(v - __half2float(h));
}

// ---------------------------------------------------------------------------
// Dense fp16 HMMA GEMM body (2-term error-compensated A split, single fp16 B)
// C[m][n] = cs * sum_k A[m][k]*B[n][k].  Tile 128x128, K-chunk 32, 2-stage.
// ---------------------------------------------------------------------------
#define TSTRIDE 80
#define TILEB   (128 * TSTRIDE)

template<int TERMS, typename CT>
__device__ __forceinline__ void gemm_body(
    const __half* __restrict__ Ah, const __half* __restrict__ Al, int lda,
    const __half* __restrict__ B, int ldb,
    CT* __restrict__ C, int ldc, int K, float cs)
{
    constexpr int STAGEB = (TERMS + 1) * TILEB;
    constexpr int OFF_B  = TERMS * TILEB;

    extern __shared__ char smem[];
    const u32 sb = smem_u32(smem);

    const int tid = threadIdx.x;
    const int wid = tid >> 5;
    const int lid = tid & 31;
    const int row0 = blockIdx.y * 128;
    const int col0 = blockIdx.x * 128;
    const int wm0 = (wid & 1) * 64;
    const int wn0 = (wid >> 1) * 32;

    const int lr = tid >> 1;
    const int lq = tid & 1;
    const __half* gAh = Ah + (long long)(row0 + lr) * lda + lq * 16;
    const __half* gAl = Al + (long long)(row0 + lr) * lda + lq * 16;
    const __half* gB  = B  + (long long)(col0 + lr) * ldb + lq * 16;
    const u32 sRow = sb + (u32)(lr * TSTRIDE + lq * 32);

    const int r8  = lid & 7;
    const int seg = lid >> 3;
    const u32 aLane = (u32)(((seg & 1) * 8 + r8) * TSTRIDE + (seg >> 1) * 16);
    const u32 bLane = (u32)(r8 * TSTRIDE + (seg & 1) * 16);

    float acc[4][4][4];
#pragma unroll
    for (int mi = 0; mi < 4; mi++)
#pragma unroll
        for (int ni = 0; ni < 4; ni++)
#pragma unroll
            for (int q = 0; q < 4; q++) acc[mi][ni][q] = 0.0f;

    const int nch = K >> 5;

#define LOADC(ck, st) do {                                                    \
        const u32 s0 = sRow + (u32)(st) * STAGEB;                             \
        const long long kg = (long long)(ck) * 32;                            \
        CP16(s0, gAh + kg);  CP16(s0 + 16, gAh + kg + 8);                     \
        if (TERMS == 2) { CP16(s0 + TILEB, gAl + kg);                         \
                          CP16(s0 + TILEB + 16, gAl + kg + 8); }              \
        CP16(s0 + OFF_B, gB + kg);  CP16(s0 + OFF_B + 16, gB + kg + 8);       \
    } while (0)

    LOADC(0, 0);
    CP_COMMIT();

    for (int ck = 0; ck < nch; ck++) {
        if (ck + 1 < nch) {
            LOADC(ck + 1, (ck + 1) & 1);
            CP_COMMIT();
            CP_WAIT1();
        } else {
            CP_WAIT0();
        }
        __syncthreads();

        const u32 stg   = sb + (u32)((ck & 1) * STAGEB);
        const u32 aBase = stg + (u32)(wm0 * TSTRIDE) + aLane;
        const u32 bBase = stg + (u32)(OFF_B + wn0 * TSTRIDE) + bLane;

#pragma unroll
        for (int ks = 0; ks < 2; ks++) {
            const u32 kb = (u32)(ks * 32);
            u32 b0[4], b1[4];
#pragma unroll
            for (int ni = 0; ni < 4; ni++)
                LDSM2(b0[ni], b1[ni], bBase + kb + (u32)(ni * 8 * TSTRIDE));
#pragma unroll
            for (int t = 0; t < TERMS; t++) {
                u32 a[4][4];
#pragma unroll
                for (int mi = 0; mi < 4; mi++)
                    LDSM4(a[mi], aBase + (u32)(t * TILEB) + kb + (u32)(mi * 16 * TSTRIDE));
#pragma unroll
                for (int ni = 0; ni < 4; ni++)
#pragma unroll
                    for (int mi = 0; mi < 4; mi++)
                        MMAH(acc[mi][ni], a[mi], b0[ni], b1[ni]);
            }
        }
        __syncthreads();
    }
#undef LOADC

    const int rb = row0 + wm0 + (lid >> 2);
    const int cb = col0 + wn0 + (lid & 3) * 2;
#pragma unroll
    for (int mi = 0; mi < 4; mi++) {
#pragma unroll
        for (int ni = 0; ni < 4; ni++) {
            CT* p0 = C + (long long)(rb + mi * 16) * ldc + cb + ni * 8;
            CT* p1 = p0 + 8ll * ldc;
            if (sizeof(CT) == 2) {
                *(__half2*)p0 = __floats2half2_rn(acc[mi][ni][0] * cs, acc[mi][ni][1] * cs);
                *(__half2*)p1 = __floats2half2_rn(acc[mi][ni][2] * cs, acc[mi][ni][3] * cs);
            } else {
                *(float2*)p0 = make_float2(acc[mi][ni][0] * cs, acc[mi][ni][1] * cs);
                *(float2*)p1 = make_float2(acc[mi][ni][2] * cs, acc[mi][ni][3] * cs);
            }
        }
    }
}

// Batched QKV projection: z selects weight + destination (Q scaled by 1/8)
__global__ __launch_bounds__(256, 2)
void qkv_gemm()
{
    const int z = blockIdx.z;
    const __half* B = s_WT[z];
    __half* C = (z == 0) ? s_Qf : ((z == 1) ? s_Kf : s_Vf);
    const float cs = (z == 0) ? 0.125f : 1.0f;
    gemm_body<2, __half>(s_Xh, s_Xl, DM, B, DM, C, DM, DM, cs);
}

// Output projection
__global__ __launch_bounds__(256, 2)
void wo_gemm(float* __restrict__ out)
{
    gemm_body<2, float>(s_AOh, s_AOl, DM, s_WT[3], DM, out, DM, DM, 1.0f);
}

// ---------------------------------------------------------------------------
// Fused differential attention:
//  QK^T (both variants) -> exp (no max-sub, scores bounded) -> unnormalized
//  PV accumulation O1/O2 -> combine O1/l1 - lam*O2/l2 -> GroupNorm -> *(0.2)
//  -> fp16 hi/lo split written to s_AOh/s_AOl.
// Block: 128 q-rows x 1 head. 8 warps x m16. K/V tiles (128 keys) double-buffered.
// ---------------------------------------------------------------------------
#define SQROWB 272                  // 128 halfs + 16B pad
#define SQB    (128 * SQROWB)       // 34816
#define STGB   (2 * SQB)            // K tile + V tile per stage

__device__ __forceinline__ void attn_tile_variant(
    int v, u32 sQ, u32 sK, u32 sV, u32 aOff, u32 bOff, u32 vOff,
    float (&O)[16][4], float& lA, float& lB)
{
    float accS[16][4];
#pragma unroll
    for (int ni = 0; ni < 16; ni++)
#pragma unroll
        for (int q = 0; q < 4; q++) accS[ni][q] = 0.0f;

    // --- S = Q_v * K_v^T  (m16 x n128 x k64) ---
#pragma unroll
    for (int kt = 0; kt < 4; kt++) {
        u32 a[4];
        LDSM4(a, sQ + aOff + (u32)(v * 128 + kt * 32));
#pragma unroll
        for (int np = 0; np < 8; np++) {
            u32 b[4];
            LDSM4(b, sK + bOff + (u32)(np * 4352 + v * 128 + kt * 32));
            MMAH(accS[2 * np],     a, b[0], b[1]);
            MMAH(accS[2 * np + 1], a, b[2], b[3]);
        }
    }

    // --- p = exp(s), row-sums, pack fp16 A-fragments ---
    u32 ph[16][2];
    float sa = 0.0f, sbv = 0.0f;
#pragma unroll
    for (int ni = 0; ni < 16; ni++) {
        float e0 = __expf(accS[ni][0]);
        float e1 = __expf(accS[ni][1]);
        float e2 = __expf(accS[ni][2]);
        float e3 = __expf(accS[ni][3]);
        sa  += e0 + e1;
        sbv += e2 + e3;
        ph[ni][0] = packh2(e0, e1);
        ph[ni][1] = packh2(e2, e3);
    }
    lA += sa;
    lB += sbv;

    // --- O += p * V  (m16 x n128 x k128), V via ldmatrix.trans ---
#pragma unroll
    for (int kt = 0; kt < 8; kt++) {
        u32 a[4] = { ph[2 * kt][0], ph[2 * kt][1], ph[2 * kt + 1][0], ph[2 * kt + 1][1] };
#pragma unroll
        for (int cp = 0; cp < 8; cp++) {
            u32 d[4];
            LDSM4T(d, sV + vOff + (u32)(kt * 4352 + cp * 32));
            MMAH(O[2 * cp],     a, d[0], d[1]);
            MMAH(O[2 * cp + 1], a, d[2], d[3]);
        }
    }
}

__global__ __launch_bounds__(256, 1)
void attn_fused(const float* __restrict__ gnw, const float* __restrict__ gnb)
{
    extern __shared__ char sm[];
    const u32 sb = smem_u32(sm);
    const u32 sQ = sb;
    float* shw = (float*)(sm + SQB + 2 * STGB);

    const int tid = threadIdx.x;
    const int wid = tid >> 5;
    const int lid = tid & 31;
    const int q0 = blockIdx.x * 128;
    const int h  = blockIdx.y;

    if (tid < 128) {
        shw[tid]       = gnw[h * 128 + tid];
        shw[128 + tid] = gnb[h * 128 + tid];
    }

    // --- loaders ---
    const int lr = tid >> 1, lq = tid & 1;
    const u32 sRow = (u32)(lr * SQROWB + lq * 128);
    {
        const __half* gq = s_Qf + (long long)(q0 + lr) * DM + h * 128 + lq * 64;
#pragma unroll
        for (int j = 0; j < 8; j++) CP16(sQ + sRow + j * 16, gq + j * 8);
        CP_COMMIT();
    }
    const __half* gK0 = s_Kf + (long long)lr * DM + h * 128 + lq * 64;
    const __half* gV0 = s_Vf + (long long)lr * DM + h * 128 + lq * 64;

#define LOADKV(t, st) do {                                                    \
        const u32 d = sb + SQB + (u32)(st) * STGB + sRow;                     \
        const __half* gk = gK0 + (long long)(t) * 128 * DM;                   \
        const __half* gv = gV0 + (long long)(t) * 128 * DM;                   \
        _Pragma("unroll")                                                     \
        for (int j = 0; j < 8; j++) {                                         \
            CP16(d + j * 16, gk + j * 8);                                     \
            CP16(d + SQB + j * 16, gv + j * 8);                               \
        }                                                                     \
        CP_COMMIT();                                                          \
    } while (0)

    LOADKV(0, 0);

    // --- fragment lane offsets ---
    const int r8  = lid & 7;
    const int seg = lid >> 3;
    const u32 aOff = (u32)((wid * 16 + (seg & 1) * 8 + r8) * SQROWB + (seg >> 1) * 16);
    const u32 bOff = (u32)(((lid >> 4) * 8 + r8) * SQROWB + ((lid >> 3) & 1) * 16);
    const u32 vOff = (u32)((((lid >> 3) & 1) * 8 + r8) * SQROWB + (lid >> 4) * 16);

    float O1[16][4], O2[16][4];
#pragma unroll
    for (int ni = 0; ni < 16; ni++)
#pragma unroll
        for (int q = 0; q < 4; q++) { O1[ni][q] = 0.0f; O2[ni][q] = 0.0f; }
    float l1a = 0.0f, l1b = 0.0f, l2a = 0.0f, l2b = 0.0f;

    for (int t = 0; t < 16; t++) {
        __syncthreads();
        if (t < 15) { LOADKV(t + 1, (t + 1) & 1); CP_WAIT1(); }
        else        { CP_WAIT0(); }
        __syncthreads();

        const u32 sK = sb + SQB + (u32)(t & 1) * STGB;
        const u32 sV = sK + SQB;

        attn_tile_variant(0, sQ, sK, sV, aOff, bOff, vOff, O1, l1a, l1b);
        attn_tile_variant(1, sQ, sK, sV, aOff, bOff, vOff, O2, l2a, l2b);
    }
#undef LOADKV

    // --- finish row sums across the quad ---
#pragma unroll
    for (int o = 1; o <= 2; o <<= 1) {
        l1a += __shfl_xor_sync(0xffffffffu, l1a, o);
        l1b += __shfl_xor_sync(0xffffffffu, l1b, o);
        l2a += __shfl_xor_sync(0xffffffffu, l2a, o);
        l2b += __shfl_xor_sync(0xffffffffu, l2b, o);
    }

    const float lam = g_lambda;
    const float i1a = 1.0f / l1a, i1b = 1.0f / l1b;
    const float i2a = lam / l2a,  i2b = lam / l2b;

    // --- combine + GroupNorm stats ---
    float su0 = 0.0f, su1 = 0.0f, sq0 = 0.0f, sq1 = 0.0f;
#pragma unroll
    for (int ni = 0; ni < 16; ni++) {
        float v0 = O1[ni][0] * i1a - O2[ni][0] * i2a;
        float v1 = O1[ni][1] * i1a - O2[ni][1] * i2a;
        float v2 = O1[ni][2] * i1b - O2[ni][2] * i2b;
        float v3 = O1[ni][3] * i1b - O2[ni][3] * i2b;
        O1[ni][0] = v0; O1[ni][1] = v1; O1[ni][2] = v2; O1[ni][3] = v3;
        su0 += v0 + v1;  sq0 += v0 * v0 + v1 * v1;
        su1 += v2 + v3;  sq1 += v2 * v2 + v3 * v3;
    }
#pragma unroll
    for (int o = 1; o <= 2; o <<= 1) {
        su0 += __shfl_xor_sync(0xffffffffu, su0, o);
        su1 += __shfl_xor_sync(0xffffffffu, su1, o);
        sq0 += __shfl_xor_sync(0xffffffffu, sq0, o);
        sq1 += __shfl_xor_sync(0xffffffffu, sq1, o);
    }
    const float mn0 = su0 * (1.0f / 128.0f);
    const float mn1 = su1 * (1.0f / 128.0f);
    const float iv0 = rsqrtf(sq0 * (1.0f / 128.0f) - mn0 * mn0 + 1e-5f);
    const float iv1 = rsqrtf(sq1 * (1.0f / 128.0f) - mn1 * mn1 + 1e-5f);

    const int row0 = q0 + wid * 16 + (lid >> 2);
    const float post = 1.0f - LAMBDA_INIT;
#pragma unroll
    for (int ni = 0; ni < 16; ni++) {
        const int c = ni * 8 + (lid & 3) * 2;
        const float w0 = shw[c],       w1 = shw[c + 1];
        const float b0 = shw[128 + c], b1 = shw[128 + c + 1];
        float v0 = ((O1[ni][0] - mn0) * iv0 * w0 + b0) * post;
        float v1 = ((O1[ni][1] - mn0) * iv0 * w1 + b1) * post;
        float v2 = ((O1[ni][2] - mn1) * iv1 * w0 + b0) * post;
        float v3 = ((O1[ni][3] - mn1) * iv1 * w1 + b1) * post;

        __half h0, e0, h1, e1, h2, e2, h3, e3;
        hsplit(v0, h0, e0); hsplit(v1, h1, e1);
        hsplit(v2, h2, e2); hsplit(v3, h3, e3);

        const long long off  = (long long)row0 * DM + h * 128 + c;
        const long long off2 = off + 8ll * DM;
        __half2 hh;
        hh = __halves2half2(h0, h1); *(u32*)(s_AOh + off)  = *(u32*)&hh;
        hh = __halves2half2(e0, e1); *(u32*)(s_AOl + off)  = *(u32*)&hh;
        hh = __halves2half2(h2, h3); *(u32*)(s_AOh + off2) = *(u32*)&hh;
        hh = __halves2half2(e2, e3); *(u32*)(s_AOl + off2) = *(u32*)&hh;
    }
}

// ---------------------------------------------------------------------------
// fp32 -> fp16 hi/lo split of x
// ---------------------------------------------------------------------------
__global__ __launch_bounds__(256)
void split_kernel(const float* __restrict__ src)
{
    const int i = (blockIdx.x * blockDim.x + threadIdx.x) * 4;
    float4 v = *(const float4*)(src + i);
    __half h[4], l[4];
    hsplit(v.x, h[0], l[0]);
    hsplit(v.y, h[1], l[1]);
    hsplit(v.z, h[2], l[2]);
    hsplit(v.w, h[3], l[3]);
    *(uint2*)(s_Xh + i) = *(uint2*)h;
    *(uint2*)(s_Xl + i) = *(uint2*)l;
}

// fp32 [2048][2048] -> transposed fp16, batched over the 4 weight matrices
__global__ __launch_bounds__(256)
void convT4_kernel(const float* __restrict__ w0, const float* __restrict__ w1,
                   const float* __restrict__ w2, const float* __restrict__ w3)
{
    const float* src = (blockIdx.z == 0) ? w0 : (blockIdx.z == 1) ? w1
                     : (blockIdx.z == 2) ? w2 : w3;
    __half* dst = s_WT[blockIdx.z];

    __shared__ float tile[32][33];
    const int bx = blockIdx.x * 32;
    const int by = blockIdx.y * 32;
    const int tx = threadIdx.x, ty = threadIdx.y;
#pragma unroll
    for (int i = 0; i < 32; i += 8)
        tile[ty + i][tx] = src[(long long)(by + ty + i) * DM + bx + tx];
    __syncthreads();
#pragma unroll
    for (int i = 0; i < 32; i += 8)
        dst[(long long)(bx + ty + i) * DM + by + tx] = __float2half_rn(tile[tx][ty + i]);
}

// ---------------------------------------------------------------------------
// lambda = exp(sum(lq1*lk1)) - exp(sum(lq2*lk2)) + 0.8
// ---------------------------------------------------------------------------
__global__ void lambda_kernel(const float* __restrict__ lq1, const float* __restrict__ lk1,
                              const float* __restrict__ lq2, const float* __restrict__ lk2)
{
    if (threadIdx.x == 0) {
        float a = 0.0f, b = 0.0f;
        for (int i = 0; i < 64; i++) { a += lq1[i] * lk1[i]; b += lq2[i] * lk2[i]; }
        g_lambda = expf(a) - expf(b) + LAMBDA_INIT;
    }
}

// ---------------------------------------------------------------------------
// Host launch
// ---------------------------------------------------------------------------
extern "C" void kernel_launch(void* const* d_in, const int* in_sizes, int n_in,
                              void* d_out, int out_size)
{
    (void)in_sizes; (void)n_in; (void)out_size;

    const float* x   = (const float*)d_in[0];
    const float* Wq  = (const float*)d_in[1];
    const float* Wk  = (const float*)d_in[2];
    const float* Wv  = (const float*)d_in[3];
    const float* Wo  = (const float*)d_in[4];
    const float* lq1 = (const float*)d_in[5];
    const float* lk1 = (const float*)d_in[6];
    const float* lq2 = (const float*)d_in[7];
    const float* lk2 = (const float*)d_in[8];
    const float* gnw = (const float*)d_in[9];
    const float* gnb = (const float*)d_in[10];
    float* out = (float*)d_out;

    const int SMG = 2 * 3 * TILEB;                  // 61440 (TERMS=2)
    const int SMA = SQB + 2 * STGB + 1024;          // 175104
    cudaFuncSetAttribute(qkv_gemm,   cudaFuncAttributeMaxDynamicSharedMemorySize, SMG);
    cudaFuncSetAttribute(wo_gemm,    cudaFuncAttributeMaxDynamicSharedMemorySize, SMG);
    cudaFuncSetAttribute(attn_fused, cudaFuncAttributeMaxDynamicSharedMemorySize, SMA);

    const dim3 blk(256);

    // input conversions
    split_kernel<<<NELEM / 1024, blk>>>(x);
    convT4_kernel<<<dim3(64, 64, 4), dim3(32, 8)>>>(Wq, Wk, Wv, Wo);

    // QKV projections (one batched launch, z = 0..2)
    qkv_gemm<<<dim3(16, 16, 3), blk, SMG>>>();

    lambda_kernel<<<1, 32>>>(lq1, lk1, lq2, lk2);

    // fused attention + GroupNorm + split
    attn_fused<<<dim3(16, 16), blk, SMA>>>(gnw, gnb);

    // output projection
    wo_gemm<<<dim3(16, 16), blk, SMG>>>(out);
}

// round 8
// speedup vs baseline: 5.0797x; 1.3430x over previous
#include <cuda_runtime.h>
#include <cuda_fp16.h>

#define SEQ     2048
#define DM      2048
#define NHEAD   16
#define LAMBDA_INIT 0.8f
#define NELEM   (SEQ * DM)

typedef unsigned int u32;

// ---------------- device scratch (no allocations) ----------------
__device__ __half s_Xf[NELEM];                  // x fp16
__device__ __half s_WT[4][NELEM];               // WqT,WkT,WvT,WoT fp16
__device__ __half s_Qf[NELEM];                  // Q fp16, pre-scaled 1/8
__device__ __half s_Kf[NELEM];
__device__ __half s_Vf[NELEM];
__device__ __half s_AO[NELEM];                  // attn out fp16

// ---------------- PTX helpers (sm_80+ portable) ----------------
__device__ __forceinline__ u32 smem_u32(const void* p) {
    u32 a;
    asm("{ .reg .u64 t; cvta.to.shared.u64 t, %1; cvt.u32.u64 %0, t; }" : "=r"(a) : "l"(p));
    return a;
}

#define CP16(saddr, gptr) \
    asm volatile("cp.async.cg.shared.global [%0], [%1], 16;" :: "r"((u32)(saddr)), "l"(gptr))
#define CP_COMMIT() asm volatile("cp.async.commit_group;" ::: "memory")
#define CP_WAIT0()  asm volatile("cp.async.wait_group 0;" ::: "memory")
#define CP_WAIT1()  asm volatile("cp.async.wait_group 1;" ::: "memory")

#define LDSM4(d, addr) \
    asm volatile("ldmatrix.sync.aligned.m8n8.x4.shared.b16 {%0,%1,%2,%3}, [%4];" \
        : "=r"((d)[0]), "=r"((d)[1]), "=r"((d)[2]), "=r"((d)[3]) : "r"((u32)(addr)))
#define LDSM4T(d, addr) \
    asm volatile("ldmatrix.sync.aligned.m8n8.x4.trans.shared.b16 {%0,%1,%2,%3}, [%4];" \
        : "=r"((d)[0]), "=r"((d)[1]), "=r"((d)[2]), "=r"((d)[3]) : "r"((u32)(addr)))
#define LDSM2(d0, d1, addr) \
    asm volatile("ldmatrix.sync.aligned.m8n8.x2.shared.b16 {%0,%1}, [%2];" \
        : "=r"(d0), "=r"(d1) : "r"((u32)(addr)))

#define MMAH(acc, a, b0, b1) \
    asm volatile("mma.sync.aligned.m16n8k16.row.col.f32.f16.f16.f32 " \
        "{%0,%1,%2,%3}, {%4,%5,%6,%7}, {%8,%9}, {%0,%1,%2,%3};" \
        : "+f"((acc)[0]), "+f"((acc)[1]), "+f"((acc)[2]), "+f"((acc)[3]) \
        : "r"((a)[0]), "r"((a)[1]), "r"((a)[2]), "r"((a)[3]), "r"(b0), "r"(b1))

__device__ __forceinline__ u32 packh2(float a, float b) {
    __half2 t = __floats2half2_rn(a, b);
    return *(u32*)&t;
}

// ---------------------------------------------------------------------------
// Dense fp16 HMMA GEMM body (single-term).
// C[m][n] = cs * sum_k A[m][k]*B[n][k].  Tile 128x128, K-chunk 32, 2-stage.
// ---------------------------------------------------------------------------
#define TSTRIDE 80
#define TILEB   (128 * TSTRIDE)
#define STAGEB  (2 * TILEB)
#define OFF_B   TILEB

template<typename CT>
__device__ __forceinline__ void gemm_body(
    const __half* __restrict__ A, int lda,
    const __half* __restrict__ B, int ldb,
    CT* __restrict__ C, int ldc, int K, float cs)
{
    extern __shared__ char smem[];
    const u32 sb = smem_u32(smem);

    const int tid = threadIdx.x;
    const int wid = tid >> 5;
    const int lid = tid & 31;
    const int row0 = blockIdx.y * 128;
    const int col0 = blockIdx.x * 128;
    const int wm0 = (wid & 1) * 64;
    const int wn0 = (wid >> 1) * 32;

    const int lr = tid >> 1;
    const int lq = tid & 1;
    const __half* gA = A + (long long)(row0 + lr) * lda + lq * 16;
    const __half* gB = B + (long long)(col0 + lr) * ldb + lq * 16;
    const u32 sRow = sb + (u32)(lr * TSTRIDE + lq * 32);

    const int r8  = lid & 7;
    const int seg = lid >> 3;
    const u32 aLane = (u32)(((seg & 1) * 8 + r8) * TSTRIDE + (seg >> 1) * 16);
    const u32 bLane = (u32)(r8 * TSTRIDE + (seg & 1) * 16);

    float acc[4][4][4];
#pragma unroll
    for (int mi = 0; mi < 4; mi++)
#pragma unroll
        for (int ni = 0; ni < 4; ni++)
#pragma unroll
            for (int q = 0; q < 4; q++) acc[mi][ni][q] = 0.0f;

    const int nch = K >> 5;

#define LOADC(ck, st) do {                                                    \
        const u32 s0 = sRow + (u32)(st) * STAGEB;                             \
        const long long kg = (long long)(ck) * 32;                            \
        CP16(s0, gA + kg);          CP16(s0 + 16, gA + kg + 8);               \
        CP16(s0 + OFF_B, gB + kg);  CP16(s0 + OFF_B + 16, gB + kg + 8);       \
    } while (0)

    LOADC(0, 0);
    CP_COMMIT();

    for (int ck = 0; ck < nch; ck++) {
        if (ck + 1 < nch) {
            LOADC(ck + 1, (ck + 1) & 1);
            CP_COMMIT();
            CP_WAIT1();
        } else {
            CP_WAIT0();
        }
        __syncthreads();

        const u32 stg   = sb + (u32)((ck & 1) * STAGEB);
        const u32 aBase = stg + (u32)(wm0 * TSTRIDE) + aLane;
        const u32 bBase = stg + (u32)(OFF_B + wn0 * TSTRIDE) + bLane;

#pragma unroll
        for (int ks = 0; ks < 2; ks++) {
            const u32 kb = (u32)(ks * 32);
            u32 b0[4], b1[4];
#pragma unroll
            for (int ni = 0; ni < 4; ni++)
                LDSM2(b0[ni], b1[ni], bBase + kb + (u32)(ni * 8 * TSTRIDE));
            u32 a[4][4];
#pragma unroll
            for (int mi = 0; mi < 4; mi++)
                LDSM4(a[mi], aBase + kb + (u32)(mi * 16 * TSTRIDE));
#pragma unroll
            for (int ni = 0; ni < 4; ni++)
#pragma unroll
                for (int mi = 0; mi < 4; mi++)
                    MMAH(acc[mi][ni], a[mi], b0[ni], b1[ni]);
        }
        __syncthreads();
    }
#undef LOADC

    const int rb = row0 + wm0 + (lid >> 2);
    const int cb = col0 + wn0 + (lid & 3) * 2;
#pragma unroll
    for (int mi = 0; mi < 4; mi++) {
#pragma unroll
        for (int ni = 0; ni < 4; ni++) {
            CT* p0 = C + (long long)(rb + mi * 16) * ldc + cb + ni * 8;
            CT* p1 = p0 + 8ll * ldc;
            if (sizeof(CT) == 2) {
                *(__half2*)p0 = __floats2half2_rn(acc[mi][ni][0] * cs, acc[mi][ni][1] * cs);
                *(__half2*)p1 = __floats2half2_rn(acc[mi][ni][2] * cs, acc[mi][ni][3] * cs);
            } else {
                *(float2*)p0 = make_float2(acc[mi][ni][0] * cs, acc[mi][ni][1] * cs);
                *(float2*)p1 = make_float2(acc[mi][ni][2] * cs, acc[mi][ni][3] * cs);
            }
        }
    }
}

// Batched QKV projection: z selects weight + destination (Q scaled by 1/8)
__global__ __launch_bounds__(256, 2)
void qkv_gemm()
{
    const int z = blockIdx.z;
    __half* C = (z == 0) ? s_Qf : ((z == 1) ? s_Kf : s_Vf);
    gemm_body<__half>(s_Xf, DM, s_WT[z], DM, C, DM, DM, (z == 0) ? 0.125f : 1.0f);
}

// Output projection
__global__ __launch_bounds__(256, 2)
void wo_gemm(float* __restrict__ out)
{
    gemm_body<float>(s_AO, DM, s_WT[3], DM, out, DM, DM, 1.0f);
}

// ---------------------------------------------------------------------------
// Fused differential attention:
//  QK^T (both variants) -> exp (no max-sub, scores bounded) -> unnormalized
//  PV accumulation O1/O2 -> combine O1/l1 - lam*O2/l2 -> GroupNorm -> *(0.2)
//  -> fp16 written to s_AO.  lambda computed in-block.
// Block: 128 q-rows x 1 head. 8 warps x m16. K/V tiles (128 keys) double-buffered.
// ---------------------------------------------------------------------------
#define SQROWB 272                  // 128 halfs + 16B pad
#define SQB    (128 * SQROWB)       // 34816
#define STGB   (2 * SQB)            // K tile + V tile per stage

__device__ __forceinline__ void attn_tile_variant(
    int v, u32 sQ, u32 sK, u32 sV, u32 aOff, u32 bOff, u32 vOff,
    float (&O)[16][4], float& lA, float& lB)
{
    float accS[16][4];
#pragma unroll
    for (int ni = 0; ni < 16; ni++)
#pragma unroll
        for (int q = 0; q < 4; q++) accS[ni][q] = 0.0f;

    // --- S = Q_v * K_v^T  (m16 x n128 x k64) ---
#pragma unroll
    for (int kt = 0; kt < 4; kt++) {
        u32 a[4];
        LDSM4(a, sQ + aOff + (u32)(v * 128 + kt * 32));
#pragma unroll
        for (int np = 0; np < 8; np++) {
            u32 b[4];
            LDSM4(b, sK + bOff + (u32)(np * 4352 + v * 128 + kt * 32));
            MMAH(accS[2 * np],     a, b[0], b[1]);
            MMAH(accS[2 * np + 1], a, b[2], b[3]);
        }
    }

    // --- p = exp(s), row-sums, pack fp16 A-fragments ---
    u32 ph[16][2];
    float sa = 0.0f, sbv = 0.0f;
#pragma unroll
    for (int ni = 0; ni < 16; ni++) {
        float e0 = __expf(accS[ni][0]);
        float e1 = __expf(accS[ni][1]);
        float e2 = __expf(accS[ni][2]);
        float e3 = __expf(accS[ni][3]);
        sa  += e0 + e1;
        sbv += e2 + e3;
        ph[ni][0] = packh2(e0, e1);
        ph[ni][1] = packh2(e2, e3);
    }
    lA += sa;
    lB += sbv;

    // --- O += p * V  (m16 x n128 x k128), V via ldmatrix.trans ---
#pragma unroll
    for (int kt = 0; kt < 8; kt++) {
        u32 a[4] = { ph[2 * kt][0], ph[2 * kt][1], ph[2 * kt + 1][0], ph[2 * kt + 1][1] };
#pragma unroll
        for (int cp = 0; cp < 8; cp++) {
            u32 d[4];
            LDSM4T(d, sV + vOff + (u32)(kt * 4352 + cp * 32));
            MMAH(O[2 * cp],     a, d[0], d[1]);
            MMAH(O[2 * cp + 1], a, d[2], d[3]);
        }
    }
}

__global__ __launch_bounds__(256, 1)
void attn_fused(const float* __restrict__ gnw, const float* __restrict__ gnb,
                const float* __restrict__ lq1, const float* __restrict__ lk1,
                const float* __restrict__ lq2, const float* __restrict__ lk2)
{
    extern __shared__ char sm[];
    const u32 sb = smem_u32(sm);
    const u32 sQ = sb;
    float* shw = (float*)(sm + SQB + 2 * STGB);

    const int tid = threadIdx.x;
    const int wid = tid >> 5;
    const int lid = tid & 31;
    const int q0 = blockIdx.x * 128;
    const int h  = blockIdx.y;

    if (tid < 128) {
        shw[tid]       = gnw[h * 128 + tid];
        shw[128 + tid] = gnb[h * 128 + tid];
    }
    // lambda (one warp, redundant per block)
    if (wid == 7) {
        float a = lq1[lid] * lk1[lid] + lq1[lid + 32] * lk1[lid + 32];
        float b = lq2[lid] * lk2[lid] + lq2[lid + 32] * lk2[lid + 32];
#pragma unroll
        for (int o = 16; o; o >>= 1) {
            a += __shfl_xor_sync(0xffffffffu, a, o);
            b += __shfl_xor_sync(0xffffffffu, b, o);
        }
        if (lid == 0) shw[256] = __expf(a) - __expf(b) + LAMBDA_INIT;
    }

    // --- loaders ---
    const int lr = tid >> 1, lq = tid & 1;
    const u32 sRow = (u32)(lr * SQROWB + lq * 128);
    {
        const __half* gq = s_Qf + (long long)(q0 + lr) * DM + h * 128 + lq * 64;
#pragma unroll
        for (int j = 0; j < 8; j++) CP16(sQ + sRow + j * 16, gq + j * 8);
        CP_COMMIT();
    }
    const __half* gK0 = s_Kf + (long long)lr * DM + h * 128 + lq * 64;
    const __half* gV0 = s_Vf + (long long)lr * DM + h * 128 + lq * 64;

#define LOADKV(t, st) do {                                                    \
        const u32 d = sb + SQB + (u32)(st) * STGB + sRow;                     \
        const __half* gk = gK0 + (long long)(t) * 128 * DM;                   \
        const __half* gv = gV0 + (long long)(t) * 128 * DM;                   \
        _Pragma("unroll")                                                     \
        for (int j = 0; j < 8; j++) {                                         \
            CP16(d + j * 16, gk + j * 8);                                     \
            CP16(d + SQB + j * 16, gv + j * 8);                               \
        }                                                                     \
        CP_COMMIT();                                                          \
    } while (0)

    LOADKV(0, 0);

    // --- fragment lane offsets ---
    const int r8  = lid & 7;
    const int seg = lid >> 3;
    const u32 aOff = (u32)((wid * 16 + (seg & 1) * 8 + r8) * SQROWB + (seg >> 1) * 16);
    const u32 bOff = (u32)(((lid >> 4) * 8 + r8) * SQROWB + ((lid >> 3) & 1) * 16);
    const u32 vOff = (u32)((((lid >> 3) & 1) * 8 + r8) * SQROWB + (lid >> 4) * 16);

    float O1[16][4], O2[16][4];
#pragma unroll
    for (int ni = 0; ni < 16; ni++)
#pragma unroll
        for (int q = 0; q < 4; q++) { O1[ni][q] = 0.0f; O2[ni][q] = 0.0f; }
    float l1a = 0.0f, l1b = 0.0f, l2a = 0.0f, l2b = 0.0f;

    for (int t = 0; t < 16; t++) {
        __syncthreads();
        if (t < 15) { LOADKV(t + 1, (t + 1) & 1); CP_WAIT1(); }
        else        { CP_WAIT0(); }
        __syncthreads();

        const u32 sK = sb + SQB + (u32)(t & 1) * STGB;
        const u32 sV = sK + SQB;

        attn_tile_variant(0, sQ, sK, sV, aOff, bOff, vOff, O1, l1a, l1b);
        attn_tile_variant(1, sQ, sK, sV, aOff, bOff, vOff, O2, l2a, l2b);
    }
#undef LOADKV

    // --- finish row sums across the quad ---
#pragma unroll
    for (int o = 1; o <= 2; o <<= 1) {
        l1a += __shfl_xor_sync(0xffffffffu, l1a, o);
        l1b += __shfl_xor_sync(0xffffffffu, l1b, o);
        l2a += __shfl_xor_sync(0xffffffffu, l2a, o);
        l2b += __shfl_xor_sync(0xffffffffu, l2b, o);
    }

    const float lam = shw[256];
    const float i1a = 1.0f / l1a, i1b = 1.0f / l1b;
    const float i2a = lam / l2a,  i2b = lam / l2b;

    // --- combine + GroupNorm stats ---
    float su0 = 0.0f, su1 = 0.0f, sq0 = 0.0f, sq1 = 0.0f;
#pragma unroll
    for (int ni = 0; ni < 16; ni++) {
        float v0 = O1[ni][0] * i1a - O2[ni][0] * i2a;
        float v1 = O1[ni][1] * i1a - O2[ni][1] * i2a;
        float v2 = O1[ni][2] * i1b - O2[ni][2] * i2b;
        float v3 = O1[ni][3] * i1b - O2[ni][3] * i2b;
        O1[ni][0] = v0; O1[ni][1] = v1; O1[ni][2] = v2; O1[ni][3] = v3;
        su0 += v0 + v1;  sq0 += v0 * v0 + v1 * v1;
        su1 += v2 + v3;  sq1 += v2 * v2 + v3 * v3;
    }
#pragma unroll
    for (int o = 1; o <= 2; o <<= 1) {
        su0 += __shfl_xor_sync(0xffffffffu, su0, o);
        su1 += __shfl_xor_sync(0xffffffffu, su1, o);
        sq0 += __shfl_xor_sync(0xffffffffu, sq0, o);
        sq1 += __shfl_xor_sync(0xffffffffu, sq1, o);
    }
    const float mn0 = su0 * (1.0f / 128.0f);
    const float mn1 = su1 * (1.0f / 128.0f);
    const float iv0 = rsqrtf(sq0 * (1.0f / 128.0f) - mn0 * mn0 + 1e-5f);
    const float iv1 = rsqrtf(sq1 * (1.0f / 128.0f) - mn1 * mn1 + 1e-5f);

    const int row0 = q0 + wid * 16 + (lid >> 2);
    const float post = 1.0f - LAMBDA_INIT;
#pragma unroll
    for (int ni = 0; ni < 16; ni++) {
        const int c = ni * 8 + (lid & 3) * 2;
        const float w0 = shw[c],       w1 = shw[c + 1];
        const float b0 = shw[128 + c], b1 = shw[128 + c + 1];
        float v0 = ((O1[ni][0] - mn0) * iv0 * w0 + b0) * post;
        float v1 = ((O1[ni][1] - mn0) * iv0 * w1 + b1) * post;
        float v2 = ((O1[ni][2] - mn1) * iv1 * w0 + b0) * post;
        float v3 = ((O1[ni][3] - mn1) * iv1 * w1 + b1) * post;

        const long long off = (long long)row0 * DM + h * 128 + c;
        __half2 hh;
        hh = __floats2half2_rn(v0, v1); *(u32*)(s_AO + off)           = *(u32*)&hh;
        hh = __floats2half2_rn(v2, v3); *(u32*)(s_AO + off + 8ll * DM) = *(u32*)&hh;
    }
}

// ---------------------------------------------------------------------------
// fp32 -> fp16 conversion of x
// ---------------------------------------------------------------------------
__global__ __launch_bounds__(256)
void conv_kernel(const float* __restrict__ src)
{
    const int i = (blockIdx.x * blockDim.x + threadIdx.x) * 8;
    float4 a = *(const float4*)(src + i);
    float4 b = *(const float4*)(src + i + 4);
    __half2 h[4];
    h[0] = __floats2half2_rn(a.x, a.y);
    h[1] = __floats2half2_rn(a.z, a.w);
    h[2] = __floats2half2_rn(b.x, b.y);
    h[3] = __floats2half2_rn(b.z, b.w);
    *(uint4*)(s_Xf + i) = *(uint4*)h;
}

// fp32 [2048][2048] -> transposed fp16, batched over the 4 weight matrices
__global__ __launch_bounds__(256)
void convT4_kernel(const float* __restrict__ w0, const float* __restrict__ w1,
                   const float* __restrict__ w2, const float* __restrict__ w3)
{
    const float* src = (blockIdx.z == 0) ? w0 : (blockIdx.z == 1) ? w1
                     : (blockIdx.z == 2) ? w2 : w3;
    __half* dst = s_WT[blockIdx.z];

    __shared__ float tile[32][33];
    const int bx = blockIdx.x * 32;
    const int by = blockIdx.y * 32;
    const int tx = threadIdx.x, ty = threadIdx.y;
#pragma unroll
    for (int i = 0; i < 32; i += 8)
        tile[ty + i][tx] = src[(long long)(by + ty + i) * DM + bx + tx];
    __syncthreads();
#pragma unroll
    for (int i = 0; i < 32; i += 8)
        dst[(long long)(bx + ty + i) * DM + by + tx] = __float2half_rn(tile[tx][ty + i]);
}

// ---------------------------------------------------------------------------
// Host launch
// ---------------------------------------------------------------------------
extern "C" void kernel_launch(void* const* d_in, const int* in_sizes, int n_in,
                              void* d_out, int out_size)
{
    (void)in_sizes; (void)n_in; (void)out_size;

    const float* x   = (const float*)d_in[0];
    const float* Wq  = (const float*)d_in[1];
    const float* Wk  = (const float*)d_in[2];
    const float* Wv  = (const float*)d_in[3];
    const float* Wo  = (const float*)d_in[4];
    const float* lq1 = (const float*)d_in[5];
    const float* lk1 = (const float*)d_in[6];
    const float* lq2 = (const float*)d_in[7];
    const float* lk2 = (const float*)d_in[8];
    const float* gnw = (const float*)d_in[9];
    const float* gnb = (const float*)d_in[10];
    float* out = (float*)d_out;

    const int SMG = 2 * STAGEB;                     // 40960
    const int SMA = SQB + 2 * STGB + 1088;          // ~175 KB
    cudaFuncSetAttribute(qkv_gemm,   cudaFuncAttributeMaxDynamicSharedMemorySize, SMG);
    cudaFuncSetAttribute(wo_gemm,    cudaFuncAttributeMaxDynamicSharedMemorySize, SMG);
    cudaFuncSetAttribute(attn_fused, cudaFuncAttributeMaxDynamicSharedMemorySize, SMA);

    const dim3 blk(256);

    // input conversions
    conv_kernel<<<NELEM / 2048, blk>>>(x);
    convT4_kernel<<<dim3(64, 64, 4), dim3(32, 8)>>>(Wq, Wk, Wv, Wo);

    // QKV projections (one batched launch, z = 0..2)
    qkv_gemm<<<dim3(16, 16, 3), blk, SMG>>>();

    // fused attention + GroupNorm (lambda computed in-block)
    attn_fused<<<dim3(16, 16), blk, SMA>>>(gnw, gnb, lq1, lk1, lq2, lk2);

    // output projection
    wo_gemm<<<dim3(16, 16), blk, SMG>>>(out);
}

// round 9
// speedup vs baseline: 5.5557x; 1.0937x over previous
#include <cuda_runtime.h>
#include <cuda_fp16.h>

#define SEQ     2048
#define DM      2048
#define NHEAD   16
#define LAMBDA_INIT 0.8f
#define NELEM   (SEQ * DM)

typedef unsigned int u32;

// ---------------- device scratch (no allocations) ----------------
__device__ __half s_Xf[NELEM];                  // x fp16
__device__ __half s_WT[4][NELEM];               // WqT,WkT,WvT,WoT fp16
__device__ __half s_Qf[NELEM];                  // Q fp16, pre-scaled 1/8
__device__ __half s_Kf[NELEM];
__device__ __half s_Vf[NELEM];
__device__ __half s_AO[NELEM];                  // attn out fp16

// ---------------- PTX helpers (sm_80+ portable) ----------------
__device__ __forceinline__ u32 smem_u32(const void* p) {
    u32 a;
    asm("{ .reg .u64 t; cvta.to.shared.u64 t, %1; cvt.u32.u64 %0, t; }" : "=r"(a) : "l"(p));
    return a;
}

#define CP16(saddr, gptr) \
    asm volatile("cp.async.cg.shared.global [%0], [%1], 16;" :: "r"((u32)(saddr)), "l"(gptr))
#define CP_COMMIT() asm volatile("cp.async.commit_group;" ::: "memory")
#define CP_WAIT0()  asm volatile("cp.async.wait_group 0;" ::: "memory")
#define CP_WAIT1()  asm volatile("cp.async.wait_group 1;" ::: "memory")

#define LDSM4(d, addr) \
    asm volatile("ldmatrix.sync.aligned.m8n8.x4.shared.b16 {%0,%1,%2,%3}, [%4];" \
        : "=r"((d)[0]), "=r"((d)[1]), "=r"((d)[2]), "=r"((d)[3]) : "r"((u32)(addr)))
#define LDSM4T(d, addr) \
    asm volatile("ldmatrix.sync.aligned.m8n8.x4.trans.shared.b16 {%0,%1,%2,%3}, [%4];" \
        : "=r"((d)[0]), "=r"((d)[1]), "=r"((d)[2]), "=r"((d)[3]) : "r"((u32)(addr)))
#define LDSM2(d0, d1, addr) \
    asm volatile("ldmatrix.sync.aligned.m8n8.x2.shared.b16 {%0,%1}, [%2];" \
        : "=r"(d0), "=r"(d1) : "r"((u32)(addr)))

#define MMAH(acc, a, b0, b1) \
    asm volatile("mma.sync.aligned.m16n8k16.row.col.f32.f16.f16.f32 " \
        "{%0,%1,%2,%3}, {%4,%5,%6,%7}, {%8,%9}, {%0,%1,%2,%3};" \
        : "+f"((acc)[0]), "+f"((acc)[1]), "+f"((acc)[2]), "+f"((acc)[3]) \
        : "r"((a)[0]), "r"((a)[1]), "r"((a)[2]), "r"((a)[3]), "r"(b0), "r"(b1))

__device__ __forceinline__ u32 packh2(float a, float b) {
    __half2 t = __floats2half2_rn(a, b);
    return *(u32*)&t;
}

// ---------------------------------------------------------------------------
// Dense fp16 HMMA GEMM body (single-term).
// C[m][n] = cs * sum_k A[m][k]*B[n][k].  Tile 128x128, K-chunk 32, 2-stage.
// ---------------------------------------------------------------------------
#define TSTRIDE 80
#define TILEB   (128 * TSTRIDE)
#define STAGEB  (2 * TILEB)
#define OFF_B   TILEB

template<typename CT>
__device__ __forceinline__ void gemm_body(
    const __half* __restrict__ A, int lda,
    const __half* __restrict__ B, int ldb,
    CT* __restrict__ C, int ldc, int K, float cs)
{
    extern __shared__ char smem[];
    const u32 sb = smem_u32(smem);

    const int tid = threadIdx.x;
    const int wid = tid >> 5;
    const int lid = tid & 31;
    const int row0 = blockIdx.y * 128;
    const int col0 = blockIdx.x * 128;
    const int wm0 = (wid & 1) * 64;
    const int wn0 = (wid >> 1) * 32;

    const int lr = tid >> 1;
    const int lq = tid & 1;
    const __half* gA = A + (long long)(row0 + lr) * lda + lq * 16;
    const __half* gB = B + (long long)(col0 + lr) * ldb + lq * 16;
    const u32 sRow = sb + (u32)(lr * TSTRIDE + lq * 32);

    const int r8  = lid & 7;
    const int seg = lid >> 3;
    const u32 aLane = (u32)(((seg & 1) * 8 + r8) * TSTRIDE + (seg >> 1) * 16);
    const u32 bLane = (u32)(r8 * TSTRIDE + (seg & 1) * 16);

    float acc[4][4][4];
#pragma unroll
    for (int mi = 0; mi < 4; mi++)
#pragma unroll
        for (int ni = 0; ni < 4; ni++)
#pragma unroll
            for (int q = 0; q < 4; q++) acc[mi][ni][q] = 0.0f;

    const int nch = K >> 5;

#define LOADC(ck, st) do {                                                    \
        const u32 s0 = sRow + (u32)(st) * STAGEB;                             \
        const long long kg = (long long)(ck) * 32;                            \
        CP16(s0, gA + kg);          CP16(s0 + 16, gA + kg + 8);               \
        CP16(s0 + OFF_B, gB + kg);  CP16(s0 + OFF_B + 16, gB + kg + 8);       \
    } while (0)

    LOADC(0, 0);
    CP_COMMIT();

    for (int ck = 0; ck < nch; ck++) {
        if (ck + 1 < nch) {
            LOADC(ck + 1, (ck + 1) & 1);
            CP_COMMIT();
            CP_WAIT1();
        } else {
            CP_WAIT0();
        }
        __syncthreads();

        const u32 stg   = sb + (u32)((ck & 1) * STAGEB);
        const u32 aBase = stg + (u32)(wm0 * TSTRIDE) + aLane;
        const u32 bBase = stg + (u32)(OFF_B + wn0 * TSTRIDE) + bLane;

#pragma unroll
        for (int ks = 0; ks < 2; ks++) {
            const u32 kb = (u32)(ks * 32);
            u32 b0[4], b1[4];
#pragma unroll
            for (int ni = 0; ni < 4; ni++)
                LDSM2(b0[ni], b1[ni], bBase + kb + (u32)(ni * 8 * TSTRIDE));
            u32 a[4][4];
#pragma unroll
            for (int mi = 0; mi < 4; mi++)
                LDSM4(a[mi], aBase + kb + (u32)(mi * 16 * TSTRIDE));
#pragma unroll
            for (int ni = 0; ni < 4; ni++)
#pragma unroll
                for (int mi = 0; mi < 4; mi++)
                    MMAH(acc[mi][ni], a[mi], b0[ni], b1[ni]);
        }
        __syncthreads();
    }
#undef LOADC

    const int rb = row0 + wm0 + (lid >> 2);
    const int cb = col0 + wn0 + (lid & 3) * 2;
#pragma unroll
    for (int mi = 0; mi < 4; mi++) {
#pragma unroll
        for (int ni = 0; ni < 4; ni++) {
            CT* p0 = C + (long long)(rb + mi * 16) * ldc + cb + ni * 8;
            CT* p1 = p0 + 8ll * ldc;
            if (sizeof(CT) == 2) {
                *(__half2*)p0 = __floats2half2_rn(acc[mi][ni][0] * cs, acc[mi][ni][1] * cs);
                *(__half2*)p1 = __floats2half2_rn(acc[mi][ni][2] * cs, acc[mi][ni][3] * cs);
            } else {
                *(float2*)p0 = make_float2(acc[mi][ni][0] * cs, acc[mi][ni][1] * cs);
                *(float2*)p1 = make_float2(acc[mi][ni][2] * cs, acc[mi][ni][3] * cs);
            }
        }
    }
}

// Batched QKV projection: z selects weight + destination (Q scaled by 1/8)
__global__ __launch_bounds__(256, 2)
void qkv_gemm()
{
    const int z = blockIdx.z;
    __half* C = (z == 0) ? s_Qf : ((z == 1) ? s_Kf : s_Vf);
    gemm_body<__half>(s_Xf, DM, s_WT[z], DM, C, DM, DM, (z == 0) ? 0.125f : 1.0f);
}

// Output projection
__global__ __launch_bounds__(256, 2)
void wo_gemm(float* __restrict__ out)
{
    gemm_body<float>(s_AO, DM, s_WT[3], DM, out, DM, DM, 1.0f);
}

// ---------------------------------------------------------------------------
// Fused differential attention, 512 threads:
//  warps 0-7 = variant 1, warps 8-15 = variant 2 (each m16 of 128 q rows).
//  64-key K/V tiles, double-buffered. exp without max-sub (scores bounded).
//  Combine through smem (variant-2 writes lam/l2-scaled O2 into retired KV
//  region), then GroupNorm + *(0.2) -> fp16 s_AO.  lambda computed in-block.
// ---------------------------------------------------------------------------
#define BQ     128
#define KT     64
#define QSTR   272                  // 128 halfs + 16B pad
#define SQB2   (BQ * QSTR)          // 34816
#define KTB    (KT * QSTR)          // 17408
#define STG2B  (2 * KTB)            // K + V per stage
#define FSTR   132                  // combine buffer stride (floats)

__global__ __launch_bounds__(512, 1)
void attn_fused(const float* __restrict__ gnw, const float* __restrict__ gnb,
                const float* __restrict__ lq1, const float* __restrict__ lk1,
                const float* __restrict__ lq2, const float* __restrict__ lk2)
{
    extern __shared__ char sm[];
    const u32 sb  = smem_u32(sm);
    const u32 sQ  = sb;
    const u32 sKV = sb + SQB2;
    float* fbuf = (float*)(sm + SQB2);                 // reuses KV region
    float* shw  = (float*)(sm + SQB2 + 2 * STG2B);

    const int tid = threadIdx.x;
    const int wid = tid >> 5;
    const int lid = tid & 31;
    const int q0  = blockIdx.x * BQ;
    const int h   = blockIdx.y;
    const int v   = wid >> 3;                          // variant
    const int wm  = (wid & 7) * 16;                    // warp's m-rows

    if (tid < 128) {
        shw[tid]       = gnw[h * 128 + tid];
        shw[128 + tid] = gnb[h * 128 + tid];
    }
    if (wid == 15) {
        float a = lq1[lid] * lk1[lid] + lq1[lid + 32] * lk1[lid + 32];
        float b = lq2[lid] * lk2[lid] + lq2[lid + 32] * lk2[lid + 32];
#pragma unroll
        for (int o = 16; o; o >>= 1) {
            a += __shfl_xor_sync(0xffffffffu, a, o);
            b += __shfl_xor_sync(0xffffffffu, b, o);
        }
        if (lid == 0) shw[256] = __expf(a) - __expf(b) + LAMBDA_INIT;
    }

    // --- Q loader: 512 threads, 4 CP16 each ---
    {
        const int qr = tid >> 2, qs = tid & 3;
        const __half* gq = s_Qf + (long long)(q0 + qr) * DM + h * 128 + qs * 32;
        const u32 d = sQ + (u32)(qr * QSTR + qs * 64);
#pragma unroll
        for (int j = 0; j < 4; j++) CP16(d + j * 16, gq + j * 8);
        CP_COMMIT();
    }
    // --- KV loader mapping: 8 threads/row, 2 CP16 per K and V row ---
    const int kr = tid >> 3, ks = tid & 7;
    const __half* gK0 = s_Kf + (long long)kr * DM + h * 128 + ks * 16;
    const __half* gV0 = s_Vf + (long long)kr * DM + h * 128 + ks * 16;
    const u32 kvDst = (u32)(kr * QSTR + ks * 32);

#define LOADKV(t, st) do {                                                    \
        const u32 d = sKV + (u32)(st) * STG2B + kvDst;                        \
        const __half* gk = gK0 + (long long)(t) * KT * DM;                    \
        const __half* gv = gV0 + (long long)(t) * KT * DM;                    \
        CP16(d, gk);        CP16(d + 16, gk + 8);                             \
        CP16(d + KTB, gv);  CP16(d + KTB + 16, gv + 8);                       \
        CP_COMMIT();                                                          \
    } while (0)

    LOADKV(0, 0);

    // --- fragment lane offsets ---
    const int r8  = lid & 7;
    const int seg = lid >> 3;
    const u32 aOff  = sQ + (u32)((wm + (seg & 1) * 8 + r8) * QSTR + (seg >> 1) * 16 + v * 128);
    const u32 bLane = (u32)(((lid >> 4) * 8 + r8) * QSTR + ((lid >> 3) & 1) * 16 + v * 128);
    const u32 vLane = (u32)((((lid >> 3) & 1) * 8 + r8) * QSTR + (lid >> 4) * 16);

    float O[16][4];
#pragma unroll
    for (int ni = 0; ni < 16; ni++)
#pragma unroll
        for (int q = 0; q < 4; q++) O[ni][q] = 0.0f;
    float la = 0.0f, lb = 0.0f;

#pragma unroll 1
    for (int t = 0; t < 32; t++) {
        __syncthreads();
        if (t < 31) { LOADKV(t + 1, (t + 1) & 1); CP_WAIT1(); }
        else        { CP_WAIT0(); }
        __syncthreads();

        const u32 sK = sKV + (u32)(t & 1) * STG2B;
        const u32 sV = sK + KTB;

        // --- S = Q_v * K_v^T (m16 x n64 x k64) ---
        float accS[8][4];
#pragma unroll
        for (int ni = 0; ni < 8; ni++)
#pragma unroll
            for (int q = 0; q < 4; q++) accS[ni][q] = 0.0f;

#pragma unroll
        for (int kt = 0; kt < 4; kt++) {
            u32 a[4];
            LDSM4(a, aOff + (u32)(kt * 32));
#pragma unroll
            for (int np = 0; np < 4; np++) {
                u32 b[4];
                LDSM4(b, sK + bLane + (u32)(np * 16 * QSTR + kt * 32));
                MMAH(accS[2 * np],     a, b[0], b[1]);
                MMAH(accS[2 * np + 1], a, b[2], b[3]);
            }
        }

        // --- p = exp(s), row sums, pack fp16 ---
        u32 ph[8][2];
#pragma unroll
        for (int ni = 0; ni < 8; ni++) {
            float e0 = __expf(accS[ni][0]);
            float e1 = __expf(accS[ni][1]);
            float e2 = __expf(accS[ni][2]);
            float e3 = __expf(accS[ni][3]);
            la += e0 + e1;
            lb += e2 + e3;
            ph[ni][0] = packh2(e0, e1);
            ph[ni][1] = packh2(e2, e3);
        }

        // --- O += p * V (m16 x n128 x k64), V via ldmatrix.trans ---
#pragma unroll
        for (int kt = 0; kt < 4; kt++) {
            u32 a2[4] = { ph[2 * kt][0], ph[2 * kt][1], ph[2 * kt + 1][0], ph[2 * kt + 1][1] };
#pragma unroll
            for (int cp = 0; cp < 8; cp++) {
                u32 d[4];
                LDSM4T(d, sV + vLane + (u32)(kt * 16 * QSTR + cp * 32));
                MMAH(O[2 * cp],     a2, d[0], d[1]);
                MMAH(O[2 * cp + 1], a2, d[2], d[3]);
            }
        }
    }
#undef LOADKV

    // --- finish row sums across the quad ---
#pragma unroll
    for (int o = 1; o <= 2; o <<= 1) {
        la += __shfl_xor_sync(0xffffffffu, la, o);
        lb += __shfl_xor_sync(0xffffffffu, lb, o);
    }

    __syncthreads();    // all warps done with KV smem -> fbuf reuse safe

    const int rr = wm + (lid >> 2);
    const int cq = (lid & 3) * 2;

    if (v == 1) {
        const float lam = shw[256];
        const float ia = lam / la, ib = lam / lb;
#pragma unroll
        for (int ni = 0; ni < 16; ni++) {
            *(float2*)&fbuf[rr * FSTR + ni * 8 + cq] =
                make_float2(O[ni][0] * ia, O[ni][1] * ia);
            *(float2*)&fbuf[(rr + 8) * FSTR + ni * 8 + cq] =
                make_float2(O[ni][2] * ib, O[ni][3] * ib);
        }
    } else {
        const float ia = 1.0f / la, ib = 1.0f / lb;
#pragma unroll
        for (int ni = 0; ni < 16; ni++) {
            O[ni][0] *= ia; O[ni][1] *= ia;
            O[ni][2] *= ib; O[ni][3] *= ib;
        }
    }
    __syncthreads();

    if (v == 0) {
        // combine + GroupNorm stats
        float su0 = 0.0f, su1 = 0.0f, sq0 = 0.0f, sq1 = 0.0f;
#pragma unroll
        for (int ni = 0; ni < 16; ni++) {
            float2 f0 = *(const float2*)&fbuf[rr * FSTR + ni * 8 + cq];
            float2 f1 = *(const float2*)&fbuf[(rr + 8) * FSTR + ni * 8 + cq];
            float v0 = O[ni][0] - f0.x;
            float v1 = O[ni][1] - f0.y;
            float v2 = O[ni][2] - f1.x;
            float v3 = O[ni][3] - f1.y;
            O[ni][0] = v0; O[ni][1] = v1; O[ni][2] = v2; O[ni][3] = v3;
            su0 += v0 + v1;  sq0 += v0 * v0 + v1 * v1;
            su1 += v2 + v3;  sq1 += v2 * v2 + v3 * v3;
        }
#pragma unroll
        for (int o = 1; o <= 2; o <<= 1) {
            su0 += __shfl_xor_sync(0xffffffffu, su0, o);
            su1 += __shfl_xor_sync(0xffffffffu, su1, o);
            sq0 += __shfl_xor_sync(0xffffffffu, sq0, o);
            sq1 += __shfl_xor_sync(0xffffffffu, sq1, o);
        }
        const float mn0 = su0 * (1.0f / 128.0f);
        const float mn1 = su1 * (1.0f / 128.0f);
        const float iv0 = rsqrtf(sq0 * (1.0f / 128.0f) - mn0 * mn0 + 1e-5f);
        const float iv1 = rsqrtf(sq1 * (1.0f / 128.0f) - mn1 * mn1 + 1e-5f);

        const int row0 = q0 + rr;
        const float post = 1.0f - LAMBDA_INIT;
#pragma unroll
        for (int ni = 0; ni < 16; ni++) {
            const int c = ni * 8 + cq;
            const float w0 = shw[c],       w1 = shw[c + 1];
            const float b0 = shw[128 + c], b1 = shw[128 + c + 1];
            float v0 = ((O[ni][0] - mn0) * iv0 * w0 + b0) * post;
            float v1 = ((O[ni][1] - mn0) * iv0 * w1 + b1) * post;
            float v2 = ((O[ni][2] - mn1) * iv1 * w0 + b0) * post;
            float v3 = ((O[ni][3] - mn1) * iv1 * w1 + b1) * post;

            const long long off = (long long)row0 * DM + h * 128 + c;
            __half2 hh;
            hh = __floats2half2_rn(v0, v1); *(u32*)(s_AO + off)            = *(u32*)&hh;
            hh = __floats2half2_rn(v2, v3); *(u32*)(s_AO + off + 8ll * DM) = *(u32*)&hh;
        }
    }
}

// ---------------------------------------------------------------------------
// fp32 -> fp16 conversion of x
// ---------------------------------------------------------------------------
__global__ __launch_bounds__(256)
void conv_kernel(const float* __restrict__ src)
{
    const int i = (blockIdx.x * blockDim.x + threadIdx.x) * 8;
    float4 a = *(const float4*)(src + i);
    float4 b = *(const float4*)(src + i + 4);
    __half2 h[4];
    h[0] = __floats2half2_rn(a.x, a.y);
    h[1] = __floats2half2_rn(a.z, a.w);
    h[2] = __floats2half2_rn(b.x, b.y);
    h[3] = __floats2half2_rn(b.z, b.w);
    *(uint4*)(s_Xf + i) = *(uint4*)h;
}

// fp32 [2048][2048] -> transposed fp16, batched over the 4 weight matrices
__global__ __launch_bounds__(256)
void convT4_kernel(const float* __restrict__ w0, const float* __restrict__ w1,
                   const float* __restrict__ w2, const float* __restrict__ w3)
{
    const float* src = (blockIdx.z == 0) ? w0 : (blockIdx.z == 1) ? w1
                     : (blockIdx.z == 2) ? w2 : w3;
    __half* dst = s_WT[blockIdx.z];

    __shared__ float tile[32][33];
    const int bx = blockIdx.x * 32;
    const int by = blockIdx.y * 32;
    const int tx = threadIdx.x, ty = threadIdx.y;
#pragma unroll
    for (int i = 0; i < 32; i += 8)
        tile[ty + i][tx] = src[(long long)(by + ty + i) * DM + bx + tx];
    __syncthreads();
#pragma unroll
    for (int i = 0; i < 32; i += 8)
        dst[(long long)(bx + ty + i) * DM + by + tx] = __float2half_rn(tile[tx][ty + i]);
}

// ---------------------------------------------------------------------------
// Host launch
// ---------------------------------------------------------------------------
extern "C" void kernel_launch(void* const* d_in, const int* in_sizes, int n_in,
                              void* d_out, int out_size)
{
    (void)in_sizes; (void)n_in; (void)out_size;

    const float* x   = (const float*)d_in[0];
    const float* Wq  = (const float*)d_in[1];
    const float* Wk  = (const float*)d_in[2];
    const float* Wv  = (const float*)d_in[3];
    const float* Wo  = (const float*)d_in[4];
    const float* lq1 = (const float*)d_in[5];
    const float* lk1 = (const float*)d_in[6];
    const float* lq2 = (const float*)d_in[7];
    const float* lk2 = (const float*)d_in[8];
    const float* gnw = (const float*)d_in[9];
    const float* gnb = (const float*)d_in[10];
    float* out = (float*)d_out;

    const int SMG = 2 * STAGEB;                          // 40960
    const int SMA = SQB2 + 2 * STG2B + 1088;             // ~105.5 KB
    cudaFuncSetAttribute(qkv_gemm,   cudaFuncAttributeMaxDynamicSharedMemorySize, SMG);
    cudaFuncSetAttribute(wo_gemm,    cudaFuncAttributeMaxDynamicSharedMemorySize, SMG);
    cudaFuncSetAttribute(attn_fused, cudaFuncAttributeMaxDynamicSharedMemorySize, SMA);

    const dim3 blk(256);

    // input conversions
    conv_kernel<<<NELEM / 2048, blk>>>(x);
    convT4_kernel<<<dim3(64, 64, 4), dim3(32, 8)>>>(Wq, Wk, Wv, Wo);

    // QKV projections (one batched launch, z = 0..2)
    qkv_gemm<<<dim3(16, 16, 3), blk, SMG>>>();

    // fused attention + combine + GroupNorm (lambda in-block)
    attn_fused<<<dim3(16, 16), dim3(512), SMA>>>(gnw, gnb, lq1, lk1, lq2, lk2);

    // output projection
    wo_gemm<<<dim3(16, 16), blk, SMG>>>(out);
}